// round 10
// baseline (speedup 1.0000x reference)
#include <cuda_runtime.h>
#include <cuda_bf16.h>
#include <math.h>
#include <stdint.h>

#define T_STEPS 512
#define STATE   1024
#define EMBD    512
#define VOCAB   32000
#define G4      4096   // 4*STATE

// ---------------- scratch (no allocations allowed) ----------------
__device__ float g_embs[T_STEPS * EMBD];      // gathered embeddings [T,E]
__device__ float g_gbias[G4];                 // b_ih + b_hh + W_ih[:,E:]@fixed
__device__ float g_zf[VOCAB];                 // Z @ fixed
__device__ float g_gatesx[T_STEPS * G4];      // embs @ W_ihE^T + gbias
__device__ float g_hs[T_STEPS * STATE];       // h_t outputs
// tagged h publication: [parity][1024 outputs] of float4 {h, tag, h, tag}
__device__ float4 g_tagged[2 * 1024];

// split-bf16 operands for the tensor-core scores GEMM
__device__ __nv_bfloat16 g_X_hi[VOCAB * STATE];
__device__ __nv_bfloat16 g_X_lo[VOCAB * STATE];
__device__ __nv_bfloat16 g_Y_hi[VOCAB * EMBD];
__device__ __nv_bfloat16 g_Y_lo[VOCAB * EMBD];
__device__ __nv_bfloat16 g_hs_hi[T_STEPS * STATE];
__device__ __nv_bfloat16 g_hs_lo[T_STEPS * STATE];
__device__ __nv_bfloat16 g_e_hi[T_STEPS * EMBD];
__device__ __nv_bfloat16 g_e_lo[T_STEPS * EMBD];

// ======================= PTX helpers (base-target-safe) =======================
__device__ __forceinline__ uint32_t smem_u32(const void* p) {
    uint32_t a;
    asm("{ .reg .u64 t; cvta.to.shared.u64 t, %1; cvt.u32.u64 %0, t; }" : "=r"(a) : "l"(p));
    return a;
}
__device__ __forceinline__ void cp16(uint32_t dst, const void* src) {
    asm volatile("cp.async.cg.shared.global [%0], [%1], 16;" :: "r"(dst), "l"(src));
}
#define CP_COMMIT() asm volatile("cp.async.commit_group;" ::: "memory")
#define CP_WAIT1()  asm volatile("cp.async.wait_group 1;" ::: "memory")

#define LDSM4(r, addr)                                                         \
    asm volatile("ldmatrix.sync.aligned.m8n8.x4.shared.b16 {%0,%1,%2,%3}, [%4];" \
        : "=r"((r)[0]), "=r"((r)[1]), "=r"((r)[2]), "=r"((r)[3]) : "r"(addr))

#define MMA16816(d, a, b0, b1)                                                 \
    asm volatile("mma.sync.aligned.m16n8k16.row.col.f32.bf16.bf16.f32 "        \
        "{%0,%1,%2,%3}, {%4,%5,%6,%7}, {%8,%9}, {%0,%1,%2,%3};"                \
        : "+f"((d)[0]), "+f"((d)[1]), "+f"((d)[2]), "+f"((d)[3])               \
        : "r"((a)[0]), "r"((a)[1]), "r"((a)[2]), "r"((a)[3]), "r"(b0), "r"(b1))

__device__ __forceinline__ uint32_t sw128(uint32_t off) {
    return off ^ ((off >> 3) & 0x70);
}

// ---------------- prep: gather embeddings + reset tagged slots ----------------
__global__ void prep_kernel(const int* __restrict__ ids,
                            const float* __restrict__ emb_table) {
    int t = blockIdx.x;
    int src = ids[(t == 0) ? (T_STEPS - 1) : (t - 1)];
    const float4* e = (const float4*)(emb_table + (size_t)src * EMBD);
    float4* dst = (float4*)(g_embs + t * EMBD);
    dst[threadIdx.x] = e[threadIdx.x];
    if (blockIdx.x == 0) {
#pragma unroll
        for (int i = 0; i < 16; i++)
            g_tagged[threadIdx.x * 16 + i] = make_float4(0.f, 0.f, 0.f, 0.f);
    }
}

// ---------------- fp32 -> (hi, lo) bf16 split ----------------
__global__ void conv_split_kernel(const float* __restrict__ src,
                                  __nv_bfloat16* __restrict__ hi,
                                  __nv_bfloat16* __restrict__ lo, int n4) {
    int i = blockIdx.x * blockDim.x + threadIdx.x;
    if (i >= n4) return;
    float4 v = ((const float4*)src)[i];
    __nv_bfloat16 h0 = __float2bfloat16(v.x);
    __nv_bfloat16 h1 = __float2bfloat16(v.y);
    __nv_bfloat16 h2 = __float2bfloat16(v.z);
    __nv_bfloat16 h3 = __float2bfloat16(v.w);
    __nv_bfloat16 l0 = __float2bfloat16(v.x - __bfloat162float(h0));
    __nv_bfloat16 l1 = __float2bfloat16(v.y - __bfloat162float(h1));
    __nv_bfloat16 l2 = __float2bfloat16(v.z - __bfloat162float(h2));
    __nv_bfloat16 l3 = __float2bfloat16(v.w - __bfloat162float(h3));
    ((__nv_bfloat162*)hi)[2 * i]     = __nv_bfloat162(h0, h1);
    ((__nv_bfloat162*)hi)[2 * i + 1] = __nv_bfloat162(h2, h3);
    ((__nv_bfloat162*)lo)[2 * i]     = __nv_bfloat162(l0, l1);
    ((__nv_bfloat162*)lo)[2 * i + 1] = __nv_bfloat162(l2, l3);
}

// ---------------- row-dot vs fixed=[h0,c0]: one warp per row ----------------
__global__ void rowdot_kernel(const float* __restrict__ Mat, int ldm4,
                              const float* __restrict__ vA,
                              const float* __restrict__ vB,
                              const float* __restrict__ add0,
                              const float* __restrict__ add1,
                              float* __restrict__ out) {
    __shared__ float v[2048];
    for (int i = threadIdx.x; i < 2048; i += blockDim.x)
        v[i] = (i < 1024) ? vA[i] : vB[i - 1024];
    __syncthreads();
    int warp = threadIdx.x >> 5, lane = threadIdx.x & 31;
    int row = blockIdx.x * 8 + warp;
    const float4* m4 = (const float4*)Mat + (size_t)row * ldm4;
    const float4* v4 = (const float4*)v;
    float s = 0.f;
#pragma unroll
    for (int i = 0; i < 16; i++) {
        float4 a = m4[i * 32 + lane];
        float4 b = v4[i * 32 + lane];
        s += a.x * b.x + a.y * b.y + a.z * b.z + a.w * b.w;
    }
#pragma unroll
    for (int o = 16; o; o >>= 1) s += __shfl_xor_sync(0xffffffffu, s, o);
    if (lane == 0) {
        if (add0) s += add0[row];
        if (add1) s += add1[row];
        out[row] = s;
    }
}

// ---------------- FFMA SGEMM for gates_x: C = A*B^T + bias ----------
__global__ __launch_bounds__(256, 2)
void sgemm_bt_kernel(const float* __restrict__ A1, int lda1, int K1,
                     const float* __restrict__ B1, int ldb1,
                     const float* __restrict__ bias,
                     float* __restrict__ C, int ldc) {
    __shared__ float As[16][128];
    __shared__ float Bs[16][128];
    const int tid = threadIdx.x;
    const int tx = tid & 15, ty = tid >> 4;
    const int m0 = blockIdx.x * 128, n0 = blockIdx.y * 128;
    const int lr = tid >> 2;
    const int lc = (tid & 3) * 4;

    float acc[8][8];
#pragma unroll
    for (int i = 0; i < 8; i++)
#pragma unroll
        for (int j = 0; j < 8; j++) acc[i][j] = 0.f;

    const float* ap0 = A1 + (size_t)(m0 + lr) * lda1 + lc;
    const float* ap1 = ap0 + (size_t)64 * lda1;
    const float* bp0 = B1 + (size_t)(n0 + lr) * ldb1 + lc;
    const float* bp1 = bp0 + (size_t)64 * ldb1;
    float4 ra0 = *(const float4*)ap0;
    float4 ra1 = *(const float4*)ap1;
    float4 rb0 = *(const float4*)bp0;
    float4 rb1 = *(const float4*)bp1;
    const int KT = K1 >> 4;
    for (int kt = 0; kt < KT; kt++) {
        As[lc + 0][lr] = ra0.x; As[lc + 1][lr] = ra0.y;
        As[lc + 2][lr] = ra0.z; As[lc + 3][lr] = ra0.w;
        As[lc + 0][lr + 64] = ra1.x; As[lc + 1][lr + 64] = ra1.y;
        As[lc + 2][lr + 64] = ra1.z; As[lc + 3][lr + 64] = ra1.w;
        Bs[lc + 0][lr] = rb0.x; Bs[lc + 1][lr] = rb0.y;
        Bs[lc + 2][lr] = rb0.z; Bs[lc + 3][lr] = rb0.w;
        Bs[lc + 0][lr + 64] = rb1.x; Bs[lc + 1][lr + 64] = rb1.y;
        Bs[lc + 2][lr + 64] = rb1.z; Bs[lc + 3][lr + 64] = rb1.w;
        __syncthreads();
        if (kt + 1 < KT) {
            ap0 += 16; ap1 += 16; bp0 += 16; bp1 += 16;
            ra0 = *(const float4*)ap0;
            ra1 = *(const float4*)ap1;
            rb0 = *(const float4*)bp0;
            rb1 = *(const float4*)bp1;
        }
#pragma unroll
        for (int k = 0; k < 16; k++) {
            float4 af0 = *(const float4*)&As[k][ty * 4];
            float4 af1 = *(const float4*)&As[k][ty * 4 + 64];
            float4 bf0 = *(const float4*)&Bs[k][tx * 4];
            float4 bf1 = *(const float4*)&Bs[k][tx * 4 + 64];
            float a_[8] = {af0.x, af0.y, af0.z, af0.w, af1.x, af1.y, af1.z, af1.w};
            float b_[8] = {bf0.x, bf0.y, bf0.z, bf0.w, bf1.x, bf1.y, bf1.z, bf1.w};
#pragma unroll
            for (int i = 0; i < 8; i++)
#pragma unroll
                for (int j = 0; j < 8; j++) acc[i][j] += a_[i] * b_[j];
        }
        __syncthreads();
    }

    float4 bv0 = *(const float4*)&bias[n0 + tx * 4];
    float4 bv1 = *(const float4*)&bias[n0 + tx * 4 + 64];
#pragma unroll
    for (int i = 0; i < 8; i++) {
        int m = m0 + ((i < 4) ? (ty * 4 + i) : (64 + ty * 4 + i - 4));
        float4 r0 = make_float4(acc[i][0] + bv0.x, acc[i][1] + bv0.y,
                                acc[i][2] + bv0.z, acc[i][3] + bv0.w);
        float4 r1 = make_float4(acc[i][4] + bv1.x, acc[i][5] + bv1.y,
                                acc[i][6] + bv1.z, acc[i][7] + bv1.w);
        *(float4*)&C[(size_t)m * ldc + n0 + tx * 4] = r0;
        *(float4*)&C[(size_t)m * ldc + n0 + tx * 4 + 64] = r1;
    }
}

// ---------------- persistent LSTM scan v5: warp-per-output ----------
// 128 CTAs x 256 threads. Warp j owns output base_j+j. Lane = (gate g = lane>>3,
// k-segment kseg = lane&7). Butterfly reduce within octets -> parallel MUFU
// activations on lanes 0/8/16/24 -> lane 0 updates c, publishes {h,tag,h,tag}.
// No psum array; end-of-step barrier sits after the publish (off critical path).
__global__ __launch_bounds__(256, 1)
void scan_kernel(const float* __restrict__ W_hh, const float* __restrict__ h0,
                 const float* __restrict__ c0) {
    __shared__ float4 h4s[256];
    float* hf = (float*)h4s;

    const int tid = threadIdx.x;
    const int bid = blockIdx.x;
    const int base_j = bid * 8;
    const int j = tid >> 5;          // warp = output index (0..7)
    const int lane = tid & 31;
    const int g = lane >> 3;         // gate 0..3 (i,f,g,o)
    const int kseg = lane & 7;       // k-segment (128 floats)
    const int grow = (g << 10) + base_j + j;   // W_hh / gatesx row

    float4 wreg[32];
    {
        const float4* src = (const float4*)W_hh + (size_t)grow * 256 + kseg * 32;
#pragma unroll
        for (int i = 0; i < 32; i++) wreg[i] = src[i];
    }
    float c_reg = (lane == 0) ? c0[base_j + j] : 0.f;
    __syncthreads();

#pragma unroll 1
    for (int t = 0; t < T_STEPS; t++) {
        float gx = g_gatesx[(size_t)t * G4 + grow];   // issue early

        if (t == 0) {
            h4s[tid] = ((const float4*)h0)[tid];
        } else {
            const unsigned int want = (unsigned int)t;
            const float4* pb = g_tagged + (((t - 1) & 1) << 10);
            const float4* p0 = pb + tid;
            const float4* p1 = pb + tid + 256;
            const float4* p2 = pb + tid + 512;
            const float4* p3 = pb + tid + 768;
            float4 a0, a1, a2, a3;
            int d0 = 0, d1 = 0, d2 = 0, d3 = 0;
            do {
                if (!d0) {
                    asm volatile("ld.volatile.global.v4.f32 {%0,%1,%2,%3}, [%4];"
                                 : "=f"(a0.x), "=f"(a0.y), "=f"(a0.z), "=f"(a0.w)
                                 : "l"(p0));
                    d0 = (__float_as_uint(a0.y) >= want) &&
                         (__float_as_uint(a0.w) >= want);
                }
                if (!d1) {
                    asm volatile("ld.volatile.global.v4.f32 {%0,%1,%2,%3}, [%4];"
                                 : "=f"(a1.x), "=f"(a1.y), "=f"(a1.z), "=f"(a1.w)
                                 : "l"(p1));
                    d1 = (__float_as_uint(a1.y) >= want) &&
                         (__float_as_uint(a1.w) >= want);
                }
                if (!d2) {
                    asm volatile("ld.volatile.global.v4.f32 {%0,%1,%2,%3}, [%4];"
                                 : "=f"(a2.x), "=f"(a2.y), "=f"(a2.z), "=f"(a2.w)
                                 : "l"(p2));
                    d2 = (__float_as_uint(a2.y) >= want) &&
                         (__float_as_uint(a2.w) >= want);
                }
                if (!d3) {
                    asm volatile("ld.volatile.global.v4.f32 {%0,%1,%2,%3}, [%4];"
                                 : "=f"(a3.x), "=f"(a3.y), "=f"(a3.z), "=f"(a3.w)
                                 : "l"(p3));
                    d3 = (__float_as_uint(a3.y) >= want) &&
                         (__float_as_uint(a3.w) >= want);
                }
            } while (!(d0 && d1 && d2 && d3));
            hf[tid] = a0.x;
            hf[tid + 256] = a1.x;
            hf[tid + 512] = a2.x;
            hf[tid + 768] = a3.x;
        }
        __syncthreads();   // h4s ready

        // FFMA over this lane's 128-float k-segment
        const float4* hseg = &h4s[kseg * 32];
        float4 av = make_float4(0.f, 0.f, 0.f, 0.f);
#pragma unroll
        for (int i = 0; i < 32; i++) {
            float4 b = hseg[i];
            av.x += wreg[i].x * b.x; av.y += wreg[i].y * b.y;
            av.z += wreg[i].z * b.z; av.w += wreg[i].w * b.w;
        }
        float s = (av.x + av.y) + (av.z + av.w);
        // butterfly over kseg bits: all 8 lanes of the octet get the row sum
        s += __shfl_xor_sync(0xffffffffu, s, 1);
        s += __shfl_xor_sync(0xffffffffu, s, 2);
        s += __shfl_xor_sync(0xffffffffu, s, 4);
        s += gx;

        // branch-free activation (tanh for gate 2, sigmoid otherwise)
        float scale = (g == 2) ? 2.f * s : s;
        float sig = 1.f / (1.f + __expf(-scale));
        float act = (g == 2) ? (2.f * sig - 1.f) : sig;

        float iv = __shfl_sync(0xffffffffu, act, 0);
        float fv = __shfl_sync(0xffffffffu, act, 8);
        float gv = __shfl_sync(0xffffffffu, act, 16);
        float ov = __shfl_sync(0xffffffffu, act, 24);

        if (lane == 0) {
            c_reg = fv * c_reg + iv * gv;
            float tc = 2.f / (1.f + __expf(-2.f * c_reg)) - 1.f;
            float hval = ov * tc;
            g_hs[(size_t)t * STATE + base_j + j] = hval;
            float tagf = __uint_as_float((unsigned int)(t + 1));
            float4* dst = g_tagged + ((t & 1) << 10) + base_j + j;
            asm volatile("st.volatile.global.v4.f32 [%0], {%1,%2,%3,%4};"
                         :: "l"(dst), "f"(hval), "f"(tagf), "f"(hval), "f"(tagf)
                         : "memory");
        }
        __syncthreads();   // protect h4s; publish already in flight
    }
}

// ============== mma.sync split-bf16 scores GEMM ==============
#define TILE_B  16384u
#define STAGE_B (4u * TILE_B)
#define SCORES_SMEM (2 * STAGE_B)
#define NCHUNK 24

__device__ __forceinline__ void load_stage(const __nv_bfloat16* Ah,
                                           const __nv_bfloat16* Al,
                                           const __nv_bfloat16* Bh,
                                           const __nv_bfloat16* Bl,
                                           int ld, int m0, int n0, int k0,
                                           uint32_t stage, int tid) {
#pragma unroll
    for (int i = 0; i < 16; i++) {
        int id = tid + (i << 8);
        int tile = id >> 10;
        int within = id & 1023;
        int row = within >> 3;
        int c = within & 7;
        const __nv_bfloat16* bp = (tile == 0) ? Ah : (tile == 1) ? Al
                                 : (tile == 2) ? Bh : Bl;
        int grow = ((tile < 2) ? m0 : n0) + row;
        const __nv_bfloat16* src = bp + (size_t)grow * ld + k0 + (c << 3);
        uint32_t dst = stage + ((uint32_t)tile << 14)
                     + sw128(((uint32_t)row << 7) + ((uint32_t)c << 4));
        cp16(dst, src);
    }
}

__global__ __launch_bounds__(256, 1)
void scores_mma_kernel(const __nv_bfloat16* __restrict__ Ah,
                       const __nv_bfloat16* __restrict__ Al,
                       const __nv_bfloat16* __restrict__ Xh,
                       const __nv_bfloat16* __restrict__ Xl,
                       const __nv_bfloat16* __restrict__ Eh,
                       const __nv_bfloat16* __restrict__ El,
                       const __nv_bfloat16* __restrict__ Yh,
                       const __nv_bfloat16* __restrict__ Yl,
                       const float* __restrict__ zf,
                       float* __restrict__ out) {
    extern __shared__ __align__(16) char dsm[];
    uint32_t base = smem_u32(dsm);
    const int tid = threadIdx.x, wid = tid >> 5, lane = tid & 31;
    const int m0 = blockIdx.x * 128, n0 = blockIdx.y * 128;
    const int wm = (wid & 3) * 32;
    const int wn = (wid >> 2) * 64;

    float acc[2][8][4];
#pragma unroll
    for (int a = 0; a < 2; a++)
#pragma unroll
        for (int b = 0; b < 8; b++)
#pragma unroll
            for (int c = 0; c < 4; c++) acc[a][b][c] = 0.f;

    load_stage(Ah, Al, Xh, Xl, STATE, m0, n0, 0, base, tid);
    CP_COMMIT();
    load_stage(Ah, Al, Xh, Xl, STATE, m0, n0, 64, base + STAGE_B, tid);
    CP_COMMIT();

#pragma unroll 1
    for (int s = 0; s < NCHUNK; s++) {
        uint32_t stg = base + (uint32_t)(s & 1) * STAGE_B;
        CP_WAIT1();
        __syncthreads();
#pragma unroll
        for (int ks = 0; ks < 4; ks++) {
            uint32_t kbyte = ((uint32_t)ks << 5) + (((uint32_t)lane >> 4) << 4);
            uint32_t bh[4][4], bl[4][4];
#pragma unroll
            for (int q = 0; q < 4; q++) {
                uint32_t roff = ((uint32_t)(wn + q * 16 + (lane & 15))) << 7;
                LDSM4(bh[q], stg + (2u << 14) + sw128(roff + kbyte));
                LDSM4(bl[q], stg + (3u << 14) + sw128(roff + kbyte));
            }
#pragma unroll
            for (int mt = 0; mt < 2; mt++) {
                uint32_t roff = ((uint32_t)(wm + mt * 16 + (lane & 15))) << 7;
                uint32_t a_h[4], a_l[4];
                LDSM4(a_h, stg + sw128(roff + kbyte));
                LDSM4(a_l, stg + (1u << 14) + sw128(roff + kbyte));
#pragma unroll
                for (int q = 0; q < 4; q++) {
#pragma unroll
                    for (int h = 0; h < 2; h++) {
                        int nt = q * 2 + h;
                        MMA16816(acc[mt][nt], a_h, bh[q][h], bh[q][h + 2]);
                        MMA16816(acc[mt][nt], a_h, bl[q][h], bl[q][h + 2]);
                        MMA16816(acc[mt][nt], a_l, bh[q][h], bh[q][h + 2]);
                    }
                }
            }
        }
        __syncthreads();
        if (s + 2 < NCHUNK) {
            int s2 = s + 2;
            if (s2 < 16)
                load_stage(Ah, Al, Xh, Xl, STATE, m0, n0, s2 * 64, stg, tid);
            else
                load_stage(Eh, El, Yh, Yl, EMBD, m0, n0, (s2 - 16) * 64, stg, tid);
            CP_COMMIT();
        }
    }

#pragma unroll
    for (int mt = 0; mt < 2; mt++) {
        int mrow = m0 + wm + mt * 16 + (lane >> 2);
#pragma unroll
        for (int half = 0; half < 2; half++) {
            float* orow = out + (size_t)(mrow + half * 8) * VOCAB;
#pragma unroll
            for (int nt = 0; nt < 8; nt++) {
                int n = n0 + wn + nt * 8 + (lane & 3) * 2;
                float2 z = *(const float2*)&zf[n];
                float2 r;
                r.x = acc[mt][nt][half * 2 + 0] + z.x;
                r.y = acc[mt][nt][half * 2 + 1] + z.y;
                *(float2*)&orow[n] = r;
            }
        }
    }
}

// ---------------- launch ----------------
extern "C" void kernel_launch(void* const* d_in, const int* in_sizes, int n_in,
                              void* d_out, int out_size) {
    (void)in_sizes; (void)n_in; (void)out_size;
    const float* h0   = (const float*)d_in[0];
    const float* c0   = (const float*)d_in[1];
    const int*   ids  = (const int*)d_in[2];
    const float* embT = (const float*)d_in[3];
    const float* W_ih = (const float*)d_in[4];
    const float* W_hh = (const float*)d_in[5];
    const float* b_ih = (const float*)d_in[6];
    const float* b_hh = (const float*)d_in[7];
    const float* X    = (const float*)d_in[8];
    const float* Y    = (const float*)d_in[9];
    const float* Z    = (const float*)d_in[10];
    float* out = (float*)d_out;

    float *p_embs, *p_gbias, *p_zf, *p_gatesx, *p_hs;
    cudaGetSymbolAddress((void**)&p_embs, g_embs);
    cudaGetSymbolAddress((void**)&p_gbias, g_gbias);
    cudaGetSymbolAddress((void**)&p_zf, g_zf);
    cudaGetSymbolAddress((void**)&p_gatesx, g_gatesx);
    cudaGetSymbolAddress((void**)&p_hs, g_hs);
    __nv_bfloat16 *pXh, *pXl, *pYh, *pYl, *pHh, *pHl, *pEh, *pEl;
    cudaGetSymbolAddress((void**)&pXh, g_X_hi);
    cudaGetSymbolAddress((void**)&pXl, g_X_lo);
    cudaGetSymbolAddress((void**)&pYh, g_Y_hi);
    cudaGetSymbolAddress((void**)&pYl, g_Y_lo);
    cudaGetSymbolAddress((void**)&pHh, g_hs_hi);
    cudaGetSymbolAddress((void**)&pHl, g_hs_lo);
    cudaGetSymbolAddress((void**)&pEh, g_e_hi);
    cudaGetSymbolAddress((void**)&pEl, g_e_lo);

    // 1) gather embeddings, reset tagged slots
    prep_kernel<<<T_STEPS, 128>>>(ids, embT);

    // 2) gbias = b_ih + b_hh + W_ih[:,E:] @ fixed
    rowdot_kernel<<<G4 / 8, 256>>>(W_ih + EMBD, (EMBD + 2 * STATE) / 4,
                                   h0, c0, b_ih, b_hh, p_gbias);

    // 3) zf = Z @ fixed
    rowdot_kernel<<<VOCAB / 8, 256>>>(Z, (2 * STATE) / 4,
                                      h0, c0, nullptr, nullptr, p_zf);

    // 4) split conversions for X, Y, embs
    conv_split_kernel<<<(VOCAB * STATE / 4 + 255) / 256, 256>>>(X, pXh, pXl,
                                                                VOCAB * STATE / 4);
    conv_split_kernel<<<(VOCAB * EMBD / 4 + 255) / 256, 256>>>(Y, pYh, pYl,
                                                               VOCAB * EMBD / 4);
    conv_split_kernel<<<(T_STEPS * EMBD / 4 + 255) / 256, 256>>>(p_embs, pEh, pEl,
                                                                 T_STEPS * EMBD / 4);

    // 5) gates_x = embs @ W_ihE^T + gbias   [512 x 4096]
    {
        dim3 grid(T_STEPS / 128, G4 / 128);
        sgemm_bt_kernel<<<grid, 256>>>(p_embs, EMBD, EMBD,
                                       W_ih, EMBD + 2 * STATE,
                                       p_gbias, p_gatesx, G4);
    }

    // 6) sequential LSTM scan (warp-per-output, tagged publication)
    scan_kernel<<<128, 256>>>(W_hh, h0, c0);

    // 7) hs -> hi/lo bf16
    conv_split_kernel<<<(T_STEPS * STATE / 4 + 255) / 256, 256>>>(p_hs, pHh, pHl,
                                                                  T_STEPS * STATE / 4);

    // 8) scores = hs@X^T + embs@Y^T + zf via mma.sync split-bf16
    {
        cudaFuncSetAttribute(scores_mma_kernel,
                             cudaFuncAttributeMaxDynamicSharedMemorySize, SCORES_SMEM);
        dim3 grid(T_STEPS / 128, VOCAB / 128);
        scores_mma_kernel<<<grid, 256, SCORES_SMEM>>>(pHh, pHl, pXh, pXl,
                                                      pEh, pEl, pYh, pYl,
                                                      p_zf, out);
    }
}

// round 11
// speedup vs baseline: 2.6389x; 2.6389x over previous
#include <cuda_runtime.h>
#include <cuda_bf16.h>
#include <math.h>
#include <stdint.h>

#define T_STEPS 512
#define STATE   1024
#define EMBD    512
#define VOCAB   32000
#define G4      4096   // 4*STATE

// ---------------- scratch (no allocations allowed) ----------------
__device__ float g_embs[T_STEPS * EMBD];      // gathered embeddings [T,E]
__device__ float g_gbias[G4];                 // b_ih + b_hh + W_ih[:,E:]@fixed
__device__ float g_zf[VOCAB];                 // Z @ fixed
__device__ float g_gatesx[T_STEPS * G4];      // embs @ W_ihE^T + gbias
__device__ float g_hs[T_STEPS * STATE];       // h_t outputs
// tagged h publication: [parity][cta][4 x float4 {h_even, tag, h_odd, tag}]
__device__ float4 g_tagged[2 * 128 * 4];

// split-bf16 operands for the tensor-core scores GEMM
__device__ __nv_bfloat16 g_X_hi[VOCAB * STATE];
__device__ __nv_bfloat16 g_X_lo[VOCAB * STATE];
__device__ __nv_bfloat16 g_Y_hi[VOCAB * EMBD];
__device__ __nv_bfloat16 g_Y_lo[VOCAB * EMBD];
__device__ __nv_bfloat16 g_hs_hi[T_STEPS * STATE];
__device__ __nv_bfloat16 g_hs_lo[T_STEPS * STATE];
__device__ __nv_bfloat16 g_e_hi[T_STEPS * EMBD];
__device__ __nv_bfloat16 g_e_lo[T_STEPS * EMBD];

// ======================= PTX helpers (base-target-safe) =======================
__device__ __forceinline__ uint32_t smem_u32(const void* p) {
    uint32_t a;
    asm("{ .reg .u64 t; cvta.to.shared.u64 t, %1; cvt.u32.u64 %0, t; }" : "=r"(a) : "l"(p));
    return a;
}
__device__ __forceinline__ void cp16(uint32_t dst, const void* src) {
    asm volatile("cp.async.cg.shared.global [%0], [%1], 16;" :: "r"(dst), "l"(src));
}
#define CP_COMMIT() asm volatile("cp.async.commit_group;" ::: "memory")
#define CP_WAIT1()  asm volatile("cp.async.wait_group 1;" ::: "memory")

#define LDSM4(r, addr)                                                         \
    asm volatile("ldmatrix.sync.aligned.m8n8.x4.shared.b16 {%0,%1,%2,%3}, [%4];" \
        : "=r"((r)[0]), "=r"((r)[1]), "=r"((r)[2]), "=r"((r)[3]) : "r"(addr))

#define MMA16816(d, a, b0, b1)                                                 \
    asm volatile("mma.sync.aligned.m16n8k16.row.col.f32.bf16.bf16.f32 "        \
        "{%0,%1,%2,%3}, {%4,%5,%6,%7}, {%8,%9}, {%0,%1,%2,%3};"                \
        : "+f"((d)[0]), "+f"((d)[1]), "+f"((d)[2]), "+f"((d)[3])               \
        : "r"((a)[0]), "r"((a)[1]), "r"((a)[2]), "r"((a)[3]), "r"(b0), "r"(b1))

__device__ __forceinline__ uint32_t sw128(uint32_t off) {
    return off ^ ((off >> 3) & 0x70);
}

// ---------------- prep: gather embeddings + reset tagged slots ----------------
__global__ void prep_kernel(const int* __restrict__ ids,
                            const float* __restrict__ emb_table) {
    int t = blockIdx.x;
    int src = ids[(t == 0) ? (T_STEPS - 1) : (t - 1)];
    const float4* e = (const float4*)(emb_table + (size_t)src * EMBD);
    float4* dst = (float4*)(g_embs + t * EMBD);
    dst[threadIdx.x] = e[threadIdx.x];
    if (blockIdx.x == 0) {
#pragma unroll
        for (int i = 0; i < 8; i++)
            g_tagged[threadIdx.x * 8 + i] = make_float4(0.f, 0.f, 0.f, 0.f);
    }
}

// ---------------- fp32 -> (hi, lo) bf16 split ----------------
__global__ void conv_split_kernel(const float* __restrict__ src,
                                  __nv_bfloat16* __restrict__ hi,
                                  __nv_bfloat16* __restrict__ lo, int n4) {
    int i = blockIdx.x * blockDim.x + threadIdx.x;
    if (i >= n4) return;
    float4 v = ((const float4*)src)[i];
    __nv_bfloat16 h0 = __float2bfloat16(v.x);
    __nv_bfloat16 h1 = __float2bfloat16(v.y);
    __nv_bfloat16 h2 = __float2bfloat16(v.z);
    __nv_bfloat16 h3 = __float2bfloat16(v.w);
    __nv_bfloat16 l0 = __float2bfloat16(v.x - __bfloat162float(h0));
    __nv_bfloat16 l1 = __float2bfloat16(v.y - __bfloat162float(h1));
    __nv_bfloat16 l2 = __float2bfloat16(v.z - __bfloat162float(h2));
    __nv_bfloat16 l3 = __float2bfloat16(v.w - __bfloat162float(h3));
    ((__nv_bfloat162*)hi)[2 * i]     = __nv_bfloat162(h0, h1);
    ((__nv_bfloat162*)hi)[2 * i + 1] = __nv_bfloat162(h2, h3);
    ((__nv_bfloat162*)lo)[2 * i]     = __nv_bfloat162(l0, l1);
    ((__nv_bfloat162*)lo)[2 * i + 1] = __nv_bfloat162(l2, l3);
}

// ---------------- row-dot vs fixed=[h0,c0]: one warp per row ----------------
__global__ void rowdot_kernel(const float* __restrict__ Mat, int ldm4,
                              const float* __restrict__ vA,
                              const float* __restrict__ vB,
                              const float* __restrict__ add0,
                              const float* __restrict__ add1,
                              float* __restrict__ out) {
    __shared__ float v[2048];
    for (int i = threadIdx.x; i < 2048; i += blockDim.x)
        v[i] = (i < 1024) ? vA[i] : vB[i - 1024];
    __syncthreads();
    int warp = threadIdx.x >> 5, lane = threadIdx.x & 31;
    int row = blockIdx.x * 8 + warp;
    const float4* m4 = (const float4*)Mat + (size_t)row * ldm4;
    const float4* v4 = (const float4*)v;
    float s = 0.f;
#pragma unroll
    for (int i = 0; i < 16; i++) {
        float4 a = m4[i * 32 + lane];
        float4 b = v4[i * 32 + lane];
        s += a.x * b.x + a.y * b.y + a.z * b.z + a.w * b.w;
    }
#pragma unroll
    for (int o = 16; o; o >>= 1) s += __shfl_xor_sync(0xffffffffu, s, o);
    if (lane == 0) {
        if (add0) s += add0[row];
        if (add1) s += add1[row];
        out[row] = s;
    }
}

// ---------------- FFMA SGEMM for gates_x: C = A*B^T + bias ----------
__global__ __launch_bounds__(256, 2)
void sgemm_bt_kernel(const float* __restrict__ A1, int lda1, int K1,
                     const float* __restrict__ B1, int ldb1,
                     const float* __restrict__ bias,
                     float* __restrict__ C, int ldc) {
    __shared__ float As[16][128];
    __shared__ float Bs[16][128];
    const int tid = threadIdx.x;
    const int tx = tid & 15, ty = tid >> 4;
    const int m0 = blockIdx.x * 128, n0 = blockIdx.y * 128;
    const int lr = tid >> 2;
    const int lc = (tid & 3) * 4;

    float acc[8][8];
#pragma unroll
    for (int i = 0; i < 8; i++)
#pragma unroll
        for (int j = 0; j < 8; j++) acc[i][j] = 0.f;

    const float* ap0 = A1 + (size_t)(m0 + lr) * lda1 + lc;
    const float* ap1 = ap0 + (size_t)64 * lda1;
    const float* bp0 = B1 + (size_t)(n0 + lr) * ldb1 + lc;
    const float* bp1 = bp0 + (size_t)64 * ldb1;
    float4 ra0 = *(const float4*)ap0;
    float4 ra1 = *(const float4*)ap1;
    float4 rb0 = *(const float4*)bp0;
    float4 rb1 = *(const float4*)bp1;
    const int KT = K1 >> 4;
    for (int kt = 0; kt < KT; kt++) {
        As[lc + 0][lr] = ra0.x; As[lc + 1][lr] = ra0.y;
        As[lc + 2][lr] = ra0.z; As[lc + 3][lr] = ra0.w;
        As[lc + 0][lr + 64] = ra1.x; As[lc + 1][lr + 64] = ra1.y;
        As[lc + 2][lr + 64] = ra1.z; As[lc + 3][lr + 64] = ra1.w;
        Bs[lc + 0][lr] = rb0.x; Bs[lc + 1][lr] = rb0.y;
        Bs[lc + 2][lr] = rb0.z; Bs[lc + 3][lr] = rb0.w;
        Bs[lc + 0][lr + 64] = rb1.x; Bs[lc + 1][lr + 64] = rb1.y;
        Bs[lc + 2][lr + 64] = rb1.z; Bs[lc + 3][lr + 64] = rb1.w;
        __syncthreads();
        if (kt + 1 < KT) {
            ap0 += 16; ap1 += 16; bp0 += 16; bp1 += 16;
            ra0 = *(const float4*)ap0;
            ra1 = *(const float4*)ap1;
            rb0 = *(const float4*)bp0;
            rb1 = *(const float4*)bp1;
        }
#pragma unroll
        for (int k = 0; k < 16; k++) {
            float4 af0 = *(const float4*)&As[k][ty * 4];
            float4 af1 = *(const float4*)&As[k][ty * 4 + 64];
            float4 bf0 = *(const float4*)&Bs[k][tx * 4];
            float4 bf1 = *(const float4*)&Bs[k][tx * 4 + 64];
            float a_[8] = {af0.x, af0.y, af0.z, af0.w, af1.x, af1.y, af1.z, af1.w};
            float b_[8] = {bf0.x, bf0.y, bf0.z, bf0.w, bf1.x, bf1.y, bf1.z, bf1.w};
#pragma unroll
            for (int i = 0; i < 8; i++)
#pragma unroll
                for (int j = 0; j < 8; j++) acc[i][j] += a_[i] * b_[j];
        }
        __syncthreads();
    }

    float4 bv0 = *(const float4*)&bias[n0 + tx * 4];
    float4 bv1 = *(const float4*)&bias[n0 + tx * 4 + 64];
#pragma unroll
    for (int i = 0; i < 8; i++) {
        int m = m0 + ((i < 4) ? (ty * 4 + i) : (64 + ty * 4 + i - 4));
        float4 r0 = make_float4(acc[i][0] + bv0.x, acc[i][1] + bv0.y,
                                acc[i][2] + bv0.z, acc[i][3] + bv0.w);
        float4 r1 = make_float4(acc[i][4] + bv1.x, acc[i][5] + bv1.y,
                                acc[i][6] + bv1.z, acc[i][7] + bv1.w);
        *(float4*)&C[(size_t)m * ldc + n0 + tx * 4] = r0;
        *(float4*)&C[(size_t)m * ldc + n0 + tx * 4 + 64] = r1;
    }
}

// ---------------- persistent LSTM scan v6: v4 structure, 512 threads ----------
// 128 CTAs x 512 threads. Same publication scheme as v4 (4 vectors/CTA, 512
// slots). Thread t: row r = t&31 (gate r>>3, output r&7), k-segment seg = t>>5
// (16 segs of 64 floats). Each thread holds 64 weight floats and polls exactly
// ONE tagged slot.
__global__ __launch_bounds__(512, 1)
void scan_kernel(const float* __restrict__ W_hh, const float* __restrict__ h0,
                 const float* __restrict__ c0) {
    __shared__ float4 h4s[256];
    __shared__ float psum[32 * 17];
    float* hf = (float*)h4s;

    const int tid = threadIdx.x;
    const int bid = blockIdx.x;
    const int base_j = bid * 8;
    const int r = tid & 31;
    const int seg = tid >> 5;                    // 0..15
    const int gr = ((r >> 3) << 10) + base_j + (r & 7);

    float4 wreg[16];
    {
        const float4* src = (const float4*)W_hh + (size_t)gr * 256 + seg * 16;
#pragma unroll
        for (int i = 0; i < 16; i++) wreg[i] = src[i];
    }
    float c_reg = (tid < 8) ? c0[base_j + tid] : 0.f;
    __syncthreads();

#pragma unroll 1
    for (int t = 0; t < T_STEPS; t++) {
        float gx = 0.f;
        if (tid < 32)
            gx = g_gatesx[(size_t)t * G4 + ((tid >> 3) << 10) + base_j + (tid & 7)];

        if (t == 0) {
            if (tid < 256) h4s[tid] = ((const float4*)h0)[tid];
        } else {
            const unsigned int want = (unsigned int)t;
            const float4* p0 = g_tagged + (((t - 1) & 1) << 9) + tid;
            float4 a0 = make_float4(0, 0, 0, 0);
            int d0 = 0;
            do {
                asm volatile("ld.volatile.global.v4.f32 {%0,%1,%2,%3}, [%4];"
                             : "=f"(a0.x), "=f"(a0.y), "=f"(a0.z), "=f"(a0.w)
                             : "l"(p0));
                d0 = (__float_as_uint(a0.y) >= want) &&
                     (__float_as_uint(a0.w) >= want);
            } while (!d0);
            hf[2 * tid] = a0.x;
            hf[2 * tid + 1] = a0.z;
        }
        __syncthreads();   // h4s ready

        const float4* hseg = &h4s[seg * 16];
        float4 av = make_float4(0.f, 0.f, 0.f, 0.f);
#pragma unroll
        for (int i = 0; i < 16; i++) {
            float4 b = hseg[i];
            av.x += wreg[i].x * b.x; av.y += wreg[i].y * b.y;
            av.z += wreg[i].z * b.z; av.w += wreg[i].w * b.w;
        }
        psum[r * 17 + seg] = (av.x + av.y) + (av.z + av.w);
        __syncthreads();   // psum ready

        if (tid < 32) {
            float s = gx;
#pragma unroll
            for (int q = 0; q < 16; q++) s += psum[tid * 17 + q];
            int j = tid & 7;
            float s_i = __shfl_sync(0xffffffffu, s, j);
            float s_f = __shfl_sync(0xffffffffu, s, j + 8);
            float s_g = __shfl_sync(0xffffffffu, s, j + 16);
            float s_o = __shfl_sync(0xffffffffu, s, j + 24);
            float hval = 0.f;
            if (tid < 8) {
                float iv = 1.f / (1.f + __expf(-s_i));
                float fv = 1.f / (1.f + __expf(-s_f));
                float gv = 2.f / (1.f + __expf(-2.f * s_g)) - 1.f;
                float ov = 1.f / (1.f + __expf(-s_o));
                c_reg = fv * c_reg + iv * gv;
                float tc = 2.f / (1.f + __expf(-2.f * c_reg)) - 1.f;
                hval = ov * tc;
                g_hs[(size_t)t * STATE + base_j + tid] = hval;
            }
            float h_e = __shfl_sync(0xffffffffu, hval, tid * 2);
            float h_o = __shfl_sync(0xffffffffu, hval, tid * 2 + 1);
            if (tid < 4) {
                float tagf = __uint_as_float((unsigned int)(t + 1));
                float4* dst = g_tagged + ((t & 1) << 9) + bid * 4 + tid;
                asm volatile("st.volatile.global.v4.f32 [%0], {%1,%2,%3,%4};"
                             :: "l"(dst), "f"(h_e), "f"(tagf), "f"(h_o), "f"(tagf)
                             : "memory");
            }
        }
        // no end-of-step barrier: other warps proceed straight to next poll
    }
}

// ============== mma.sync split-bf16 scores GEMM ==============
#define TILE_B  16384u
#define STAGE_B (4u * TILE_B)
#define SCORES_SMEM (2 * STAGE_B)
#define NCHUNK 24

__device__ __forceinline__ void load_stage(const __nv_bfloat16* Ah,
                                           const __nv_bfloat16* Al,
                                           const __nv_bfloat16* Bh,
                                           const __nv_bfloat16* Bl,
                                           int ld, int m0, int n0, int k0,
                                           uint32_t stage, int tid) {
#pragma unroll
    for (int i = 0; i < 16; i++) {
        int id = tid + (i << 8);
        int tile = id >> 10;
        int within = id & 1023;
        int row = within >> 3;
        int c = within & 7;
        const __nv_bfloat16* bp = (tile == 0) ? Ah : (tile == 1) ? Al
                                 : (tile == 2) ? Bh : Bl;
        int grow = ((tile < 2) ? m0 : n0) + row;
        const __nv_bfloat16* src = bp + (size_t)grow * ld + k0 + (c << 3);
        uint32_t dst = stage + ((uint32_t)tile << 14)
                     + sw128(((uint32_t)row << 7) + ((uint32_t)c << 4));
        cp16(dst, src);
    }
}

__global__ __launch_bounds__(256, 1)
void scores_mma_kernel(const __nv_bfloat16* __restrict__ Ah,
                       const __nv_bfloat16* __restrict__ Al,
                       const __nv_bfloat16* __restrict__ Xh,
                       const __nv_bfloat16* __restrict__ Xl,
                       const __nv_bfloat16* __restrict__ Eh,
                       const __nv_bfloat16* __restrict__ El,
                       const __nv_bfloat16* __restrict__ Yh,
                       const __nv_bfloat16* __restrict__ Yl,
                       const float* __restrict__ zf,
                       float* __restrict__ out) {
    extern __shared__ __align__(16) char dsm[];
    uint32_t base = smem_u32(dsm);
    const int tid = threadIdx.x, wid = tid >> 5, lane = tid & 31;
    const int m0 = blockIdx.x * 128, n0 = blockIdx.y * 128;
    const int wm = (wid & 3) * 32;
    const int wn = (wid >> 2) * 64;

    float acc[2][8][4];
#pragma unroll
    for (int a = 0; a < 2; a++)
#pragma unroll
        for (int b = 0; b < 8; b++)
#pragma unroll
            for (int c = 0; c < 4; c++) acc[a][b][c] = 0.f;

    load_stage(Ah, Al, Xh, Xl, STATE, m0, n0, 0, base, tid);
    CP_COMMIT();
    load_stage(Ah, Al, Xh, Xl, STATE, m0, n0, 64, base + STAGE_B, tid);
    CP_COMMIT();

#pragma unroll 1
    for (int s = 0; s < NCHUNK; s++) {
        uint32_t stg = base + (uint32_t)(s & 1) * STAGE_B;
        CP_WAIT1();
        __syncthreads();
#pragma unroll
        for (int ks = 0; ks < 4; ks++) {
            uint32_t kbyte = ((uint32_t)ks << 5) + (((uint32_t)lane >> 4) << 4);
            uint32_t bh[4][4], bl[4][4];
#pragma unroll
            for (int q = 0; q < 4; q++) {
                uint32_t roff = ((uint32_t)(wn + q * 16 + (lane & 15))) << 7;
                LDSM4(bh[q], stg + (2u << 14) + sw128(roff + kbyte));
                LDSM4(bl[q], stg + (3u << 14) + sw128(roff + kbyte));
            }
#pragma unroll
            for (int mt = 0; mt < 2; mt++) {
                uint32_t roff = ((uint32_t)(wm + mt * 16 + (lane & 15))) << 7;
                uint32_t a_h[4], a_l[4];
                LDSM4(a_h, stg + sw128(roff + kbyte));
                LDSM4(a_l, stg + (1u << 14) + sw128(roff + kbyte));
#pragma unroll
                for (int q = 0; q < 4; q++) {
#pragma unroll
                    for (int h = 0; h < 2; h++) {
                        int nt = q * 2 + h;
                        MMA16816(acc[mt][nt], a_h, bh[q][h], bh[q][h + 2]);
                        MMA16816(acc[mt][nt], a_h, bl[q][h], bl[q][h + 2]);
                        MMA16816(acc[mt][nt], a_l, bh[q][h], bh[q][h + 2]);
                    }
                }
            }
        }
        __syncthreads();
        if (s + 2 < NCHUNK) {
            int s2 = s + 2;
            if (s2 < 16)
                load_stage(Ah, Al, Xh, Xl, STATE, m0, n0, s2 * 64, stg, tid);
            else
                load_stage(Eh, El, Yh, Yl, EMBD, m0, n0, (s2 - 16) * 64, stg, tid);
            CP_COMMIT();
        }
    }

#pragma unroll
    for (int mt = 0; mt < 2; mt++) {
        int mrow = m0 + wm + mt * 16 + (lane >> 2);
#pragma unroll
        for (int half = 0; half < 2; half++) {
            float* orow = out + (size_t)(mrow + half * 8) * VOCAB;
#pragma unroll
            for (int nt = 0; nt < 8; nt++) {
                int n = n0 + wn + nt * 8 + (lane & 3) * 2;
                float2 z = *(const float2*)&zf[n];
                float2 r;
                r.x = acc[mt][nt][half * 2 + 0] + z.x;
                r.y = acc[mt][nt][half * 2 + 1] + z.y;
                *(float2*)&orow[n] = r;
            }
        }
    }
}

// ---------------- launch ----------------
extern "C" void kernel_launch(void* const* d_in, const int* in_sizes, int n_in,
                              void* d_out, int out_size) {
    (void)in_sizes; (void)n_in; (void)out_size;
    const float* h0   = (const float*)d_in[0];
    const float* c0   = (const float*)d_in[1];
    const int*   ids  = (const int*)d_in[2];
    const float* embT = (const float*)d_in[3];
    const float* W_ih = (const float*)d_in[4];
    const float* W_hh = (const float*)d_in[5];
    const float* b_ih = (const float*)d_in[6];
    const float* b_hh = (const float*)d_in[7];
    const float* X    = (const float*)d_in[8];
    const float* Y    = (const float*)d_in[9];
    const float* Z    = (const float*)d_in[10];
    float* out = (float*)d_out;

    float *p_embs, *p_gbias, *p_zf, *p_gatesx, *p_hs;
    cudaGetSymbolAddress((void**)&p_embs, g_embs);
    cudaGetSymbolAddress((void**)&p_gbias, g_gbias);
    cudaGetSymbolAddress((void**)&p_zf, g_zf);
    cudaGetSymbolAddress((void**)&p_gatesx, g_gatesx);
    cudaGetSymbolAddress((void**)&p_hs, g_hs);
    __nv_bfloat16 *pXh, *pXl, *pYh, *pYl, *pHh, *pHl, *pEh, *pEl;
    cudaGetSymbolAddress((void**)&pXh, g_X_hi);
    cudaGetSymbolAddress((void**)&pXl, g_X_lo);
    cudaGetSymbolAddress((void**)&pYh, g_Y_hi);
    cudaGetSymbolAddress((void**)&pYl, g_Y_lo);
    cudaGetSymbolAddress((void**)&pHh, g_hs_hi);
    cudaGetSymbolAddress((void**)&pHl, g_hs_lo);
    cudaGetSymbolAddress((void**)&pEh, g_e_hi);
    cudaGetSymbolAddress((void**)&pEl, g_e_lo);

    // 1) gather embeddings, reset tagged slots
    prep_kernel<<<T_STEPS, 128>>>(ids, embT);

    // 2) gbias = b_ih + b_hh + W_ih[:,E:] @ fixed
    rowdot_kernel<<<G4 / 8, 256>>>(W_ih + EMBD, (EMBD + 2 * STATE) / 4,
                                   h0, c0, b_ih, b_hh, p_gbias);

    // 3) zf = Z @ fixed
    rowdot_kernel<<<VOCAB / 8, 256>>>(Z, (2 * STATE) / 4,
                                      h0, c0, nullptr, nullptr, p_zf);

    // 4) split conversions for X, Y, embs
    conv_split_kernel<<<(VOCAB * STATE / 4 + 255) / 256, 256>>>(X, pXh, pXl,
                                                                VOCAB * STATE / 4);
    conv_split_kernel<<<(VOCAB * EMBD / 4 + 255) / 256, 256>>>(Y, pYh, pYl,
                                                               VOCAB * EMBD / 4);
    conv_split_kernel<<<(T_STEPS * EMBD / 4 + 255) / 256, 256>>>(p_embs, pEh, pEl,
                                                                 T_STEPS * EMBD / 4);

    // 5) gates_x = embs @ W_ihE^T + gbias   [512 x 4096]
    {
        dim3 grid(T_STEPS / 128, G4 / 128);
        sgemm_bt_kernel<<<grid, 256>>>(p_embs, EMBD, EMBD,
                                       W_ih, EMBD + 2 * STATE,
                                       p_gbias, p_gatesx, G4);
    }

    // 6) sequential LSTM scan (v4 scheme, 512 threads)
    scan_kernel<<<128, 512>>>(W_hh, h0, c0);

    // 7) hs -> hi/lo bf16
    conv_split_kernel<<<(T_STEPS * STATE / 4 + 255) / 256, 256>>>(p_hs, pHh, pHl,
                                                                  T_STEPS * STATE / 4);

    // 8) scores = hs@X^T + embs@Y^T + zf via mma.sync split-bf16
    {
        cudaFuncSetAttribute(scores_mma_kernel,
                             cudaFuncAttributeMaxDynamicSharedMemorySize, SCORES_SMEM);
        dim3 grid(T_STEPS / 128, VOCAB / 128);
        scores_mma_kernel<<<grid, 256, SCORES_SMEM>>>(pHh, pHl, pXh, pXl,
                                                      pEh, pEl, pYh, pYl,
                                                      p_zf, out);
    }
}

// round 15
// speedup vs baseline: 2.8151x; 1.0668x over previous
#include <cuda_runtime.h>
#include <cuda_bf16.h>
#include <math.h>
#include <stdint.h>

#define T_STEPS 512
#define STATE   1024
#define EMBD    512
#define VOCAB   32000
#define G4      4096   // 4*STATE

// ---------------- scratch (no allocations allowed) ----------------
__device__ float g_embs[T_STEPS * EMBD];      // gathered embeddings [T,E]
__device__ float g_gbias[G4];                 // b_ih + b_hh + W_ih[:,E:]@fixed
__device__ float g_zf[VOCAB];                 // Z @ fixed
__device__ float g_gatesx[T_STEPS * G4];      // embs @ W_ihE^T + gbias
__device__ float g_hs[T_STEPS * STATE];       // h_t outputs
// tagged h publication: [parity][cta][4 x float4 {h_even, tag, h_odd, tag}]
__device__ float4 g_tagged[2 * 128 * 4];

// split-bf16 operands for the tensor-core scores GEMM
__device__ __nv_bfloat16 g_X_hi[VOCAB * STATE];
__device__ __nv_bfloat16 g_X_lo[VOCAB * STATE];
__device__ __nv_bfloat16 g_Y_hi[VOCAB * EMBD];
__device__ __nv_bfloat16 g_Y_lo[VOCAB * EMBD];
__device__ __nv_bfloat16 g_hs_hi[T_STEPS * STATE];
__device__ __nv_bfloat16 g_hs_lo[T_STEPS * STATE];
__device__ __nv_bfloat16 g_e_hi[T_STEPS * EMBD];
__device__ __nv_bfloat16 g_e_lo[T_STEPS * EMBD];

// ======================= PTX helpers (base-target-safe) =======================
__device__ __forceinline__ uint32_t smem_u32(const void* p) {
    uint32_t a;
    asm("{ .reg .u64 t; cvta.to.shared.u64 t, %1; cvt.u32.u64 %0, t; }" : "=r"(a) : "l"(p));
    return a;
}
__device__ __forceinline__ void cp16(uint32_t dst, const void* src) {
    asm volatile("cp.async.cg.shared.global [%0], [%1], 16;" :: "r"(dst), "l"(src));
}
#define CP_COMMIT() asm volatile("cp.async.commit_group;" ::: "memory")
#define CP_WAIT1()  asm volatile("cp.async.wait_group 1;" ::: "memory")

#define LDSM4(r, addr)                                                         \
    asm volatile("ldmatrix.sync.aligned.m8n8.x4.shared.b16 {%0,%1,%2,%3}, [%4];" \
        : "=r"((r)[0]), "=r"((r)[1]), "=r"((r)[2]), "=r"((r)[3]) : "r"(addr))

#define MMA16816(d, a, b0, b1)                                                 \
    asm volatile("mma.sync.aligned.m16n8k16.row.col.f32.bf16.bf16.f32 "        \
        "{%0,%1,%2,%3}, {%4,%5,%6,%7}, {%8,%9}, {%0,%1,%2,%3};"                \
        : "+f"((d)[0]), "+f"((d)[1]), "+f"((d)[2]), "+f"((d)[3])               \
        : "r"((a)[0]), "r"((a)[1]), "r"((a)[2]), "r"((a)[3]), "r"(b0), "r"(b1))

__device__ __forceinline__ uint32_t sw128(uint32_t off) {
    return off ^ ((off >> 3) & 0x70);
}

// ---------------- prep: gather embeddings + reset tagged slots ----------------
__global__ void prep_kernel(const int* __restrict__ ids,
                            const float* __restrict__ emb_table) {
    int t = blockIdx.x;
    int src = ids[(t == 0) ? (T_STEPS - 1) : (t - 1)];
    const float4* e = (const float4*)(emb_table + (size_t)src * EMBD);
    float4* dst = (float4*)(g_embs + t * EMBD);
    dst[threadIdx.x] = e[threadIdx.x];
    if (blockIdx.x == 0) {
#pragma unroll
        for (int i = 0; i < 8; i++)
            g_tagged[threadIdx.x * 8 + i] = make_float4(0.f, 0.f, 0.f, 0.f);
    }
}

// ---------------- fp32 -> (hi, lo) bf16 split ----------------
__global__ void conv_split_kernel(const float* __restrict__ src,
                                  __nv_bfloat16* __restrict__ hi,
                                  __nv_bfloat16* __restrict__ lo, int n4) {
    int i = blockIdx.x * blockDim.x + threadIdx.x;
    if (i >= n4) return;
    float4 v = ((const float4*)src)[i];
    __nv_bfloat16 h0 = __float2bfloat16(v.x);
    __nv_bfloat16 h1 = __float2bfloat16(v.y);
    __nv_bfloat16 h2 = __float2bfloat16(v.z);
    __nv_bfloat16 h3 = __float2bfloat16(v.w);
    __nv_bfloat16 l0 = __float2bfloat16(v.x - __bfloat162float(h0));
    __nv_bfloat16 l1 = __float2bfloat16(v.y - __bfloat162float(h1));
    __nv_bfloat16 l2 = __float2bfloat16(v.z - __bfloat162float(h2));
    __nv_bfloat16 l3 = __float2bfloat16(v.w - __bfloat162float(h3));
    ((__nv_bfloat162*)hi)[2 * i]     = __nv_bfloat162(h0, h1);
    ((__nv_bfloat162*)hi)[2 * i + 1] = __nv_bfloat162(h2, h3);
    ((__nv_bfloat162*)lo)[2 * i]     = __nv_bfloat162(l0, l1);
    ((__nv_bfloat162*)lo)[2 * i + 1] = __nv_bfloat162(l2, l3);
}

// ---------------- row-dot vs fixed=[h0,c0]: one warp per row ----------------
__global__ void rowdot_kernel(const float* __restrict__ Mat, int ldm4,
                              const float* __restrict__ vA,
                              const float* __restrict__ vB,
                              const float* __restrict__ add0,
                              const float* __restrict__ add1,
                              float* __restrict__ out) {
    __shared__ float v[2048];
    for (int i = threadIdx.x; i < 2048; i += blockDim.x)
        v[i] = (i < 1024) ? vA[i] : vB[i - 1024];
    __syncthreads();
    int warp = threadIdx.x >> 5, lane = threadIdx.x & 31;
    int row = blockIdx.x * 8 + warp;
    const float4* m4 = (const float4*)Mat + (size_t)row * ldm4;
    const float4* v4 = (const float4*)v;
    float s = 0.f;
#pragma unroll
    for (int i = 0; i < 16; i++) {
        float4 a = m4[i * 32 + lane];
        float4 b = v4[i * 32 + lane];
        s += a.x * b.x + a.y * b.y + a.z * b.z + a.w * b.w;
    }
#pragma unroll
    for (int o = 16; o; o >>= 1) s += __shfl_xor_sync(0xffffffffu, s, o);
    if (lane == 0) {
        if (add0) s += add0[row];
        if (add1) s += add1[row];
        out[row] = s;
    }
}

// ---------------- FFMA SGEMM for gates_x: C = A*B^T + bias ----------
__global__ __launch_bounds__(256, 2)
void sgemm_bt_kernel(const float* __restrict__ A1, int lda1, int K1,
                     const float* __restrict__ B1, int ldb1,
                     const float* __restrict__ bias,
                     float* __restrict__ C, int ldc) {
    __shared__ float As[16][128];
    __shared__ float Bs[16][128];
    const int tid = threadIdx.x;
    const int tx = tid & 15, ty = tid >> 4;
    const int m0 = blockIdx.x * 128, n0 = blockIdx.y * 128;
    const int lr = tid >> 2;
    const int lc = (tid & 3) * 4;

    float acc[8][8];
#pragma unroll
    for (int i = 0; i < 8; i++)
#pragma unroll
        for (int j = 0; j < 8; j++) acc[i][j] = 0.f;

    const float* ap0 = A1 + (size_t)(m0 + lr) * lda1 + lc;
    const float* ap1 = ap0 + (size_t)64 * lda1;
    const float* bp0 = B1 + (size_t)(n0 + lr) * ldb1 + lc;
    const float* bp1 = bp0 + (size_t)64 * ldb1;
    float4 ra0 = *(const float4*)ap0;
    float4 ra1 = *(const float4*)ap1;
    float4 rb0 = *(const float4*)bp0;
    float4 rb1 = *(const float4*)bp1;
    const int KT = K1 >> 4;
    for (int kt = 0; kt < KT; kt++) {
        As[lc + 0][lr] = ra0.x; As[lc + 1][lr] = ra0.y;
        As[lc + 2][lr] = ra0.z; As[lc + 3][lr] = ra0.w;
        As[lc + 0][lr + 64] = ra1.x; As[lc + 1][lr + 64] = ra1.y;
        As[lc + 2][lr + 64] = ra1.z; As[lc + 3][lr + 64] = ra1.w;
        Bs[lc + 0][lr] = rb0.x; Bs[lc + 1][lr] = rb0.y;
        Bs[lc + 2][lr] = rb0.z; Bs[lc + 3][lr] = rb0.w;
        Bs[lc + 0][lr + 64] = rb1.x; Bs[lc + 1][lr + 64] = rb1.y;
        Bs[lc + 2][lr + 64] = rb1.z; Bs[lc + 3][lr + 64] = rb1.w;
        __syncthreads();
        if (kt + 1 < KT) {
            ap0 += 16; ap1 += 16; bp0 += 16; bp1 += 16;
            ra0 = *(const float4*)ap0;
            ra1 = *(const float4*)ap1;
            rb0 = *(const float4*)bp0;
            rb1 = *(const float4*)bp1;
        }
#pragma unroll
        for (int k = 0; k < 16; k++) {
            float4 af0 = *(const float4*)&As[k][ty * 4];
            float4 af1 = *(const float4*)&As[k][ty * 4 + 64];
            float4 bf0 = *(const float4*)&Bs[k][tx * 4];
            float4 bf1 = *(const float4*)&Bs[k][tx * 4 + 64];
            float a_[8] = {af0.x, af0.y, af0.z, af0.w, af1.x, af1.y, af1.z, af1.w};
            float b_[8] = {bf0.x, bf0.y, bf0.z, bf0.w, bf1.x, bf1.y, bf1.z, bf1.w};
#pragma unroll
            for (int i = 0; i < 8; i++)
#pragma unroll
                for (int j = 0; j < 8; j++) acc[i][j] += a_[i] * b_[j];
        }
        __syncthreads();
    }

    float4 bv0 = *(const float4*)&bias[n0 + tx * 4];
    float4 bv1 = *(const float4*)&bias[n0 + tx * 4 + 64];
#pragma unroll
    for (int i = 0; i < 8; i++) {
        int m = m0 + ((i < 4) ? (ty * 4 + i) : (64 + ty * 4 + i - 4));
        float4 r0 = make_float4(acc[i][0] + bv0.x, acc[i][1] + bv0.y,
                                acc[i][2] + bv0.z, acc[i][3] + bv0.w);
        float4 r1 = make_float4(acc[i][4] + bv1.x, acc[i][5] + bv1.y,
                                acc[i][6] + bv1.z, acc[i][7] + bv1.w);
        *(float4*)&C[(size_t)m * ldc + n0 + tx * 4] = r0;
        *(float4*)&C[(size_t)m * ldc + n0 + tx * 4 + 64] = r1;
    }
}

// ---------------- persistent LSTM scan v7: FFMA2 + parallel activations ------
// 128 CTAs x 512 threads, v4/v6 publication scheme unchanged. Dot products use
// packed fma.rn.f32x2 (half the FFMA issue slots); warp-0 activations computed
// in parallel across 32 lanes (one MUFU chain instead of four serial ones).
__global__ __launch_bounds__(512, 1)
void scan_kernel(const float* __restrict__ W_hh, const float* __restrict__ h0,
                 const float* __restrict__ c0) {
    __shared__ float4 h4s[256];
    __shared__ float psum[32 * 17];
    float* hf = (float*)h4s;

    const int tid = threadIdx.x;
    const int bid = blockIdx.x;
    const int base_j = bid * 8;
    const int r = tid & 31;
    const int seg = tid >> 5;                    // 0..15
    const int gr = ((r >> 3) << 10) + base_j + (r & 7);

    ulonglong2 wreg[16];   // 64 weight floats as 16x (2 packed f32x2)
    {
        const ulonglong2* src =
            (const ulonglong2*)W_hh + (size_t)gr * 256 + seg * 16;
#pragma unroll
        for (int i = 0; i < 16; i++) wreg[i] = src[i];
    }
    float c_reg = (tid < 8) ? c0[base_j + tid] : 0.f;
    __syncthreads();

#pragma unroll 1
    for (int t = 0; t < T_STEPS; t++) {
        float gx = 0.f;
        if (tid < 32)
            gx = g_gatesx[(size_t)t * G4 + ((tid >> 3) << 10) + base_j + (tid & 7)];

        if (t == 0) {
            if (tid < 256) h4s[tid] = ((const float4*)h0)[tid];
        } else {
            const unsigned int want = (unsigned int)t;
            const float4* p0 = g_tagged + (((t - 1) & 1) << 9) + tid;
            float4 a0 = make_float4(0, 0, 0, 0);
            int d0 = 0;
            do {
                asm volatile("ld.volatile.global.v4.f32 {%0,%1,%2,%3}, [%4];"
                             : "=f"(a0.x), "=f"(a0.y), "=f"(a0.z), "=f"(a0.w)
                             : "l"(p0));
                d0 = (__float_as_uint(a0.y) >= want) &&
                     (__float_as_uint(a0.w) >= want);
            } while (!d0);
            hf[2 * tid] = a0.x;
            hf[2 * tid + 1] = a0.z;
        }
        __syncthreads();   // h4s ready

        // packed-fp32 dot product over this thread's 64-float k-segment
        const ulonglong2* hseg = (const ulonglong2*)&h4s[seg * 16];
        unsigned long long acc0 = 0ull, acc1 = 0ull;   // {0.f, 0.f} packed
#pragma unroll
        for (int i = 0; i < 16; i++) {
            ulonglong2 b = hseg[i];
            ulonglong2 w = wreg[i];
            asm("fma.rn.f32x2 %0, %1, %2, %0;" : "+l"(acc0) : "l"(w.x), "l"(b.x));
            asm("fma.rn.f32x2 %0, %1, %2, %0;" : "+l"(acc1) : "l"(w.y), "l"(b.y));
        }
        float a0, a1, a2, a3;
        asm("mov.b64 {%0,%1}, %2;" : "=f"(a0), "=f"(a1) : "l"(acc0));
        asm("mov.b64 {%0,%1}, %2;" : "=f"(a2), "=f"(a3) : "l"(acc1));
        psum[r * 17 + seg] = (a0 + a1) + (a2 + a3);
        __syncthreads();   // psum ready

        if (tid < 32) {
            float s = gx;
#pragma unroll
            for (int q = 0; q < 16; q++) s += psum[tid * 17 + q];
            // parallel activation: each lane activates its own gate-row
            int g2 = tid >> 3;
            float scale = (g2 == 2) ? 2.f * s : s;
            float sig = 1.f / (1.f + __expf(-scale));
            float act = (g2 == 2) ? (2.f * sig - 1.f) : sig;
            int j = tid & 7;
            float iv = __shfl_sync(0xffffffffu, act, j);
            float fv = __shfl_sync(0xffffffffu, act, j + 8);
            float gv = __shfl_sync(0xffffffffu, act, j + 16);
            float ov = __shfl_sync(0xffffffffu, act, j + 24);
            float hval = 0.f;
            if (tid < 8) {
                c_reg = fv * c_reg + iv * gv;
                float tc = 2.f / (1.f + __expf(-2.f * c_reg)) - 1.f;
                hval = ov * tc;
                g_hs[(size_t)t * STATE + base_j + tid] = hval;
            }
            float h_e = __shfl_sync(0xffffffffu, hval, tid * 2);
            float h_o = __shfl_sync(0xffffffffu, hval, tid * 2 + 1);
            if (tid < 4) {
                float tagf = __uint_as_float((unsigned int)(t + 1));
                float4* dst = g_tagged + ((t & 1) << 9) + bid * 4 + tid;
                asm volatile("st.volatile.global.v4.f32 [%0], {%1,%2,%3,%4};"
                             :: "l"(dst), "f"(h_e), "f"(tagf), "f"(h_o), "f"(tagf)
                             : "memory");
            }
        }
        // no end-of-step barrier: other warps proceed straight to next poll
    }
}

// ============== mma.sync split-bf16 scores GEMM ==============
#define TILE_B  16384u
#define STAGE_B (4u * TILE_B)
#define SCORES_SMEM (2 * STAGE_B)
#define NCHUNK 24

__device__ __forceinline__ void load_stage(const __nv_bfloat16* Ah,
                                           const __nv_bfloat16* Al,
                                           const __nv_bfloat16* Bh,
                                           const __nv_bfloat16* Bl,
                                           int ld, int m0, int n0, int k0,
                                           uint32_t stage, int tid) {
#pragma unroll
    for (int i = 0; i < 16; i++) {
        int id = tid + (i << 8);
        int tile = id >> 10;
        int within = id & 1023;
        int row = within >> 3;
        int c = within & 7;
        const __nv_bfloat16* bp = (tile == 0) ? Ah : (tile == 1) ? Al
                                 : (tile == 2) ? Bh : Bl;
        int grow = ((tile < 2) ? m0 : n0) + row;
        const __nv_bfloat16* src = bp + (size_t)grow * ld + k0 + (c << 3);
        uint32_t dst = stage + ((uint32_t)tile << 14)
                     + sw128(((uint32_t)row << 7) + ((uint32_t)c << 4));
        cp16(dst, src);
    }
}

__global__ __launch_bounds__(256, 1)
void scores_mma_kernel(const __nv_bfloat16* __restrict__ Ah,
                       const __nv_bfloat16* __restrict__ Al,
                       const __nv_bfloat16* __restrict__ Xh,
                       const __nv_bfloat16* __restrict__ Xl,
                       const __nv_bfloat16* __restrict__ Eh,
                       const __nv_bfloat16* __restrict__ El,
                       const __nv_bfloat16* __restrict__ Yh,
                       const __nv_bfloat16* __restrict__ Yl,
                       const float* __restrict__ zf,
                       float* __restrict__ out) {
    extern __shared__ __align__(16) char dsm[];
    uint32_t base = smem_u32(dsm);
    const int tid = threadIdx.x, wid = tid >> 5, lane = tid & 31;
    const int m0 = blockIdx.x * 128, n0 = blockIdx.y * 128;
    const int wm = (wid & 3) * 32;
    const int wn = (wid >> 2) * 64;

    float acc[2][8][4];
#pragma unroll
    for (int a = 0; a < 2; a++)
#pragma unroll
        for (int b = 0; b < 8; b++)
#pragma unroll
            for (int c = 0; c < 4; c++) acc[a][b][c] = 0.f;

    load_stage(Ah, Al, Xh, Xl, STATE, m0, n0, 0, base, tid);
    CP_COMMIT();
    load_stage(Ah, Al, Xh, Xl, STATE, m0, n0, 64, base + STAGE_B, tid);
    CP_COMMIT();

#pragma unroll 1
    for (int s = 0; s < NCHUNK; s++) {
        uint32_t stg = base + (uint32_t)(s & 1) * STAGE_B;
        CP_WAIT1();
        __syncthreads();
#pragma unroll
        for (int ks = 0; ks < 4; ks++) {
            uint32_t kbyte = ((uint32_t)ks << 5) + (((uint32_t)lane >> 4) << 4);
            uint32_t bh[4][4], bl[4][4];
#pragma unroll
            for (int q = 0; q < 4; q++) {
                uint32_t roff = ((uint32_t)(wn + q * 16 + (lane & 15))) << 7;
                LDSM4(bh[q], stg + (2u << 14) + sw128(roff + kbyte));
                LDSM4(bl[q], stg + (3u << 14) + sw128(roff + kbyte));
            }
#pragma unroll
            for (int mt = 0; mt < 2; mt++) {
                uint32_t roff = ((uint32_t)(wm + mt * 16 + (lane & 15))) << 7;
                uint32_t a_h[4], a_l[4];
                LDSM4(a_h, stg + sw128(roff + kbyte));
                LDSM4(a_l, stg + (1u << 14) + sw128(roff + kbyte));
#pragma unroll
                for (int q = 0; q < 4; q++) {
#pragma unroll
                    for (int h = 0; h < 2; h++) {
                        int nt = q * 2 + h;
                        MMA16816(acc[mt][nt], a_h, bh[q][h], bh[q][h + 2]);
                        MMA16816(acc[mt][nt], a_h, bl[q][h], bl[q][h + 2]);
                        MMA16816(acc[mt][nt], a_l, bh[q][h], bh[q][h + 2]);
                    }
                }
            }
        }
        __syncthreads();
        if (s + 2 < NCHUNK) {
            int s2 = s + 2;
            if (s2 < 16)
                load_stage(Ah, Al, Xh, Xl, STATE, m0, n0, s2 * 64, stg, tid);
            else
                load_stage(Eh, El, Yh, Yl, EMBD, m0, n0, (s2 - 16) * 64, stg, tid);
            CP_COMMIT();
        }
    }

#pragma unroll
    for (int mt = 0; mt < 2; mt++) {
        int mrow = m0 + wm + mt * 16 + (lane >> 2);
#pragma unroll
        for (int half = 0; half < 2; half++) {
            float* orow = out + (size_t)(mrow + half * 8) * VOCAB;
#pragma unroll
            for (int nt = 0; nt < 8; nt++) {
                int n = n0 + wn + nt * 8 + (lane & 3) * 2;
                float2 z = *(const float2*)&zf[n];
                float2 r;
                r.x = acc[mt][nt][half * 2 + 0] + z.x;
                r.y = acc[mt][nt][half * 2 + 1] + z.y;
                *(float2*)&orow[n] = r;
            }
        }
    }
}

// ---------------- launch ----------------
extern "C" void kernel_launch(void* const* d_in, const int* in_sizes, int n_in,
                              void* d_out, int out_size) {
    (void)in_sizes; (void)n_in; (void)out_size;
    const float* h0   = (const float*)d_in[0];
    const float* c0   = (const float*)d_in[1];
    const int*   ids  = (const int*)d_in[2];
    const float* embT = (const float*)d_in[3];
    const float* W_ih = (const float*)d_in[4];
    const float* W_hh = (const float*)d_in[5];
    const float* b_ih = (const float*)d_in[6];
    const float* b_hh = (const float*)d_in[7];
    const float* X    = (const float*)d_in[8];
    const float* Y    = (const float*)d_in[9];
    const float* Z    = (const float*)d_in[10];
    float* out = (float*)d_out;

    float *p_embs, *p_gbias, *p_zf, *p_gatesx, *p_hs;
    cudaGetSymbolAddress((void**)&p_embs, g_embs);
    cudaGetSymbolAddress((void**)&p_gbias, g_gbias);
    cudaGetSymbolAddress((void**)&p_zf, g_zf);
    cudaGetSymbolAddress((void**)&p_gatesx, g_gatesx);
    cudaGetSymbolAddress((void**)&p_hs, g_hs);
    __nv_bfloat16 *pXh, *pXl, *pYh, *pYl, *pHh, *pHl, *pEh, *pEl;
    cudaGetSymbolAddress((void**)&pXh, g_X_hi);
    cudaGetSymbolAddress((void**)&pXl, g_X_lo);
    cudaGetSymbolAddress((void**)&pYh, g_Y_hi);
    cudaGetSymbolAddress((void**)&pYl, g_Y_lo);
    cudaGetSymbolAddress((void**)&pHh, g_hs_hi);
    cudaGetSymbolAddress((void**)&pHl, g_hs_lo);
    cudaGetSymbolAddress((void**)&pEh, g_e_hi);
    cudaGetSymbolAddress((void**)&pEl, g_e_lo);

    // 1) gather embeddings, reset tagged slots
    prep_kernel<<<T_STEPS, 128>>>(ids, embT);

    // 2) gbias = b_ih + b_hh + W_ih[:,E:] @ fixed
    rowdot_kernel<<<G4 / 8, 256>>>(W_ih + EMBD, (EMBD + 2 * STATE) / 4,
                                   h0, c0, b_ih, b_hh, p_gbias);

    // 3) zf = Z @ fixed
    rowdot_kernel<<<VOCAB / 8, 256>>>(Z, (2 * STATE) / 4,
                                      h0, c0, nullptr, nullptr, p_zf);

    // 4) split conversions for X, Y, embs
    conv_split_kernel<<<(VOCAB * STATE / 4 + 255) / 256, 256>>>(X, pXh, pXl,
                                                                VOCAB * STATE / 4);
    conv_split_kernel<<<(VOCAB * EMBD / 4 + 255) / 256, 256>>>(Y, pYh, pYl,
                                                               VOCAB * EMBD / 4);
    conv_split_kernel<<<(T_STEPS * EMBD / 4 + 255) / 256, 256>>>(p_embs, pEh, pEl,
                                                                 T_STEPS * EMBD / 4);

    // 5) gates_x = embs @ W_ihE^T + gbias   [512 x 4096]
    {
        dim3 grid(T_STEPS / 128, G4 / 128);
        sgemm_bt_kernel<<<grid, 256>>>(p_embs, EMBD, EMBD,
                                       W_ih, EMBD + 2 * STATE,
                                       p_gbias, p_gatesx, G4);
    }

    // 6) sequential LSTM scan (v7: FFMA2 + parallel activations)
    scan_kernel<<<128, 512>>>(W_hh, h0, c0);

    // 7) hs -> hi/lo bf16
    conv_split_kernel<<<(T_STEPS * STATE / 4 + 255) / 256, 256>>>(p_hs, pHh, pHl,
                                                                  T_STEPS * STATE / 4);

    // 8) scores = hs@X^T + embs@Y^T + zf via mma.sync split-bf16
    {
        cudaFuncSetAttribute(scores_mma_kernel,
                             cudaFuncAttributeMaxDynamicSharedMemorySize, SCORES_SMEM);
        dim3 grid(T_STEPS / 128, VOCAB / 128);
        scores_mma_kernel<<<grid, 256, SCORES_SMEM>>>(pHh, pHl, pXh, pXl,
                                                      pEh, pEl, pYh, pYl,
                                                      p_zf, out);
    }
}

// round 16
// speedup vs baseline: 3.1404x; 1.1155x over previous
#include <cuda_runtime.h>
#include <cuda_bf16.h>
#include <math.h>
#include <stdint.h>

#define T_STEPS 512
#define STATE   1024
#define EMBD    512
#define VOCAB   32000
#define G4      4096   // 4*STATE

// ---------------- scratch (no allocations allowed) ----------------
__device__ float g_embs[T_STEPS * EMBD];      // gathered embeddings [T,E]
__device__ float g_gbias[G4];                 // b_ih + b_hh + W_ih[:,E:]@fixed
__device__ float g_zf[VOCAB];                 // Z @ fixed
__device__ float g_gatesx[T_STEPS * G4];      // embs @ W_ihE^T + gbias
__device__ float g_hs[T_STEPS * STATE];       // h_t outputs
// tagged h publication: [parity][cta][4 x float4 {h_even, tag, h_odd, tag}]
__device__ float4 g_tagged[2 * 128 * 4];

// split-bf16 operands for the tensor-core GEMMs
__device__ __nv_bfloat16 g_X_hi[VOCAB * STATE];
__device__ __nv_bfloat16 g_X_lo[VOCAB * STATE];
__device__ __nv_bfloat16 g_Y_hi[VOCAB * EMBD];
__device__ __nv_bfloat16 g_Y_lo[VOCAB * EMBD];
__device__ __nv_bfloat16 g_hs_hi[T_STEPS * STATE];
__device__ __nv_bfloat16 g_hs_lo[T_STEPS * STATE];
__device__ __nv_bfloat16 g_e_hi[T_STEPS * EMBD];
__device__ __nv_bfloat16 g_e_lo[T_STEPS * EMBD];
__device__ __nv_bfloat16 g_Wx_hi[G4 * EMBD];   // W_ih[:, :EMBD] hi
__device__ __nv_bfloat16 g_Wx_lo[G4 * EMBD];   // W_ih[:, :EMBD] lo

// ======================= PTX helpers (base-target-safe) =======================
__device__ __forceinline__ uint32_t smem_u32(const void* p) {
    uint32_t a;
    asm("{ .reg .u64 t; cvta.to.shared.u64 t, %1; cvt.u32.u64 %0, t; }" : "=r"(a) : "l"(p));
    return a;
}
__device__ __forceinline__ void cp16(uint32_t dst, const void* src) {
    asm volatile("cp.async.cg.shared.global [%0], [%1], 16;" :: "r"(dst), "l"(src));
}
#define CP_COMMIT() asm volatile("cp.async.commit_group;" ::: "memory")
#define CP_WAIT1()  asm volatile("cp.async.wait_group 1;" ::: "memory")

#define LDSM4(r, addr)                                                         \
    asm volatile("ldmatrix.sync.aligned.m8n8.x4.shared.b16 {%0,%1,%2,%3}, [%4];" \
        : "=r"((r)[0]), "=r"((r)[1]), "=r"((r)[2]), "=r"((r)[3]) : "r"(addr))

#define MMA16816(d, a, b0, b1)                                                 \
    asm volatile("mma.sync.aligned.m16n8k16.row.col.f32.bf16.bf16.f32 "        \
        "{%0,%1,%2,%3}, {%4,%5,%6,%7}, {%8,%9}, {%0,%1,%2,%3};"                \
        : "+f"((d)[0]), "+f"((d)[1]), "+f"((d)[2]), "+f"((d)[3])               \
        : "r"((a)[0]), "r"((a)[1]), "r"((a)[2]), "r"((a)[3]), "r"(b0), "r"(b1))

__device__ __forceinline__ uint32_t sw128(uint32_t off) {
    return off ^ ((off >> 3) & 0x70);
}

// ---------------- prep: gather embeddings + reset tagged slots ----------------
__global__ void prep_kernel(const int* __restrict__ ids,
                            const float* __restrict__ emb_table) {
    int t = blockIdx.x;
    int src = ids[(t == 0) ? (T_STEPS - 1) : (t - 1)];
    const float4* e = (const float4*)(emb_table + (size_t)src * EMBD);
    float4* dst = (float4*)(g_embs + t * EMBD);
    dst[threadIdx.x] = e[threadIdx.x];
    if (blockIdx.x == 0) {
#pragma unroll
        for (int i = 0; i < 8; i++)
            g_tagged[threadIdx.x * 8 + i] = make_float4(0.f, 0.f, 0.f, 0.f);
    }
}

// ---------------- fp32 -> (hi, lo) bf16 split (contiguous) ----------------
__global__ void conv_split_kernel(const float* __restrict__ src,
                                  __nv_bfloat16* __restrict__ hi,
                                  __nv_bfloat16* __restrict__ lo, int n4) {
    int i = blockIdx.x * blockDim.x + threadIdx.x;
    if (i >= n4) return;
    float4 v = ((const float4*)src)[i];
    __nv_bfloat16 h0 = __float2bfloat16(v.x);
    __nv_bfloat16 h1 = __float2bfloat16(v.y);
    __nv_bfloat16 h2 = __float2bfloat16(v.z);
    __nv_bfloat16 h3 = __float2bfloat16(v.w);
    __nv_bfloat16 l0 = __float2bfloat16(v.x - __bfloat162float(h0));
    __nv_bfloat16 l1 = __float2bfloat16(v.y - __bfloat162float(h1));
    __nv_bfloat16 l2 = __float2bfloat16(v.z - __bfloat162float(h2));
    __nv_bfloat16 l3 = __float2bfloat16(v.w - __bfloat162float(h3));
    ((__nv_bfloat162*)hi)[2 * i]     = __nv_bfloat162(h0, h1);
    ((__nv_bfloat162*)hi)[2 * i + 1] = __nv_bfloat162(h2, h3);
    ((__nv_bfloat162*)lo)[2 * i]     = __nv_bfloat162(l0, l1);
    ((__nv_bfloat162*)lo)[2 * i + 1] = __nv_bfloat162(l2, l3);
}

// ---------------- fp32 -> (hi, lo) bf16 split (strided rows) ----------------
// dst row length row4 float4s; src row stride src_ld4 float4s.
__global__ void conv_split_strided_kernel(const float* __restrict__ src,
                                          int src_ld4, int row4,
                                          __nv_bfloat16* __restrict__ hi,
                                          __nv_bfloat16* __restrict__ lo, int n4) {
    int i = blockIdx.x * blockDim.x + threadIdx.x;
    if (i >= n4) return;
    int row = i / row4, c = i - row * row4;
    float4 v = ((const float4*)src)[(size_t)row * src_ld4 + c];
    __nv_bfloat16 h0 = __float2bfloat16(v.x);
    __nv_bfloat16 h1 = __float2bfloat16(v.y);
    __nv_bfloat16 h2 = __float2bfloat16(v.z);
    __nv_bfloat16 h3 = __float2bfloat16(v.w);
    __nv_bfloat16 l0 = __float2bfloat16(v.x - __bfloat162float(h0));
    __nv_bfloat16 l1 = __float2bfloat16(v.y - __bfloat162float(h1));
    __nv_bfloat16 l2 = __float2bfloat16(v.z - __bfloat162float(h2));
    __nv_bfloat16 l3 = __float2bfloat16(v.w - __bfloat162float(h3));
    ((__nv_bfloat162*)hi)[2 * i]     = __nv_bfloat162(h0, h1);
    ((__nv_bfloat162*)hi)[2 * i + 1] = __nv_bfloat162(h2, h3);
    ((__nv_bfloat162*)lo)[2 * i]     = __nv_bfloat162(l0, l1);
    ((__nv_bfloat162*)lo)[2 * i + 1] = __nv_bfloat162(l2, l3);
}

// ---------------- row-dot vs fixed=[h0,c0]: one warp per row ----------------
__global__ void rowdot_kernel(const float* __restrict__ Mat, int ldm4,
                              const float* __restrict__ vA,
                              const float* __restrict__ vB,
                              const float* __restrict__ add0,
                              const float* __restrict__ add1,
                              float* __restrict__ out) {
    __shared__ float v[2048];
    for (int i = threadIdx.x; i < 2048; i += blockDim.x)
        v[i] = (i < 1024) ? vA[i] : vB[i - 1024];
    __syncthreads();
    int warp = threadIdx.x >> 5, lane = threadIdx.x & 31;
    int row = blockIdx.x * 8 + warp;
    const float4* m4 = (const float4*)Mat + (size_t)row * ldm4;
    const float4* v4 = (const float4*)v;
    float s = 0.f;
#pragma unroll
    for (int i = 0; i < 16; i++) {
        float4 a = m4[i * 32 + lane];
        float4 b = v4[i * 32 + lane];
        s += a.x * b.x + a.y * b.y + a.z * b.z + a.w * b.w;
    }
#pragma unroll
    for (int o = 16; o; o >>= 1) s += __shfl_xor_sync(0xffffffffu, s, o);
    if (lane == 0) {
        if (add0) s += add0[row];
        if (add1) s += add1[row];
        out[row] = s;
    }
}

// ---------------- persistent LSTM scan v8: warp-local consumption ------------
// 128 CTAs x 512 threads. Warp w's lanes poll slots 32w..32w+31 (CTAs 8w..8w+7)
// which are exactly the h-values warp w consumes -> __syncwarp instead of a
// block barrier after the scatter. One block barrier/step before the reduce,
// psum parity-double-buffered for safety.
__global__ __launch_bounds__(512, 1)
void scan_kernel(const float* __restrict__ W_hh, const float* __restrict__ h0,
                 const float* __restrict__ c0) {
    __shared__ float4 h4s[256];
    __shared__ float psum[2][32 * 17];
    float* hf = (float*)h4s;

    const int tid = threadIdx.x;
    const int bid = blockIdx.x;
    const int base_j = bid * 8;
    const int r = tid & 31;          // lane = row
    const int seg = tid >> 5;        // warp = k-segment (64 floats)
    const int gr = ((r >> 3) << 10) + base_j + (r & 7);

    ulonglong2 wreg[16];   // 64 weight floats as 16x (2 packed f32x2)
    {
        const ulonglong2* src =
            (const ulonglong2*)W_hh + (size_t)gr * 256 + seg * 16;
#pragma unroll
        for (int i = 0; i < 16; i++) wreg[i] = src[i];
    }
    float c_reg = (tid < 8) ? c0[base_j + tid] : 0.f;
    __syncthreads();

#pragma unroll 1
    for (int t = 0; t < T_STEPS; t++) {
        float gx = 0.f;
        if (tid < 32)
            gx = g_gatesx[(size_t)t * G4 + ((tid >> 3) << 10) + base_j + (tid & 7)];

        if (t == 0) {
            // warp-local self-fill of this warp's h segment
            float2 v = ((const float2*)h0)[tid];
            hf[2 * tid] = v.x;
            hf[2 * tid + 1] = v.y;
        } else {
            const unsigned int want = (unsigned int)t;
            const float4* p0 = g_tagged + (((t - 1) & 1) << 9) + tid;
            float4 a0 = make_float4(0, 0, 0, 0);
            int d0 = 0;
            do {
                asm volatile("ld.volatile.global.v4.f32 {%0,%1,%2,%3}, [%4];"
                             : "=f"(a0.x), "=f"(a0.y), "=f"(a0.z), "=f"(a0.w)
                             : "l"(p0));
                d0 = (__float_as_uint(a0.y) >= want) &&
                     (__float_as_uint(a0.w) >= want);
            } while (!d0);
            hf[2 * tid] = a0.x;
            hf[2 * tid + 1] = a0.z;
        }
        __syncwarp();      // warp-local: this warp wrote exactly its own segment

        // packed-fp32 dot product over this warp's 64-float k-segment
        const ulonglong2* hseg = (const ulonglong2*)&h4s[seg * 16];
        unsigned long long acc0 = 0ull, acc1 = 0ull;
#pragma unroll
        for (int i = 0; i < 16; i++) {
            ulonglong2 b = hseg[i];
            ulonglong2 w = wreg[i];
            asm("fma.rn.f32x2 %0, %1, %2, %0;" : "+l"(acc0) : "l"(w.x), "l"(b.x));
            asm("fma.rn.f32x2 %0, %1, %2, %0;" : "+l"(acc1) : "l"(w.y), "l"(b.y));
        }
        float a0, a1, a2, a3;
        asm("mov.b64 {%0,%1}, %2;" : "=f"(a0), "=f"(a1) : "l"(acc0));
        asm("mov.b64 {%0,%1}, %2;" : "=f"(a2), "=f"(a3) : "l"(acc1));
        psum[t & 1][r * 17 + seg] = (a0 + a1) + (a2 + a3);
        __syncthreads();   // psum(t) complete; parity protects next-step writes

        if (tid < 32) {
            float s = gx;
            const float* pr = &psum[t & 1][tid * 17];
#pragma unroll
            for (int q = 0; q < 16; q++) s += pr[q];
            int g2 = tid >> 3;
            float scale = (g2 == 2) ? 2.f * s : s;
            float sig = 1.f / (1.f + __expf(-scale));
            float act = (g2 == 2) ? (2.f * sig - 1.f) : sig;
            int j = tid & 7;
            float iv = __shfl_sync(0xffffffffu, act, j);
            float fv = __shfl_sync(0xffffffffu, act, j + 8);
            float gv = __shfl_sync(0xffffffffu, act, j + 16);
            float ov = __shfl_sync(0xffffffffu, act, j + 24);
            float hval = 0.f;
            if (tid < 8) {
                c_reg = fv * c_reg + iv * gv;
                float tc = 2.f / (1.f + __expf(-2.f * c_reg)) - 1.f;
                hval = ov * tc;
                g_hs[(size_t)t * STATE + base_j + tid] = hval;
            }
            float h_e = __shfl_sync(0xffffffffu, hval, tid * 2);
            float h_o = __shfl_sync(0xffffffffu, hval, tid * 2 + 1);
            if (tid < 4) {
                float tagf = __uint_as_float((unsigned int)(t + 1));
                float4* dst = g_tagged + ((t & 1) << 9) + bid * 4 + tid;
                asm volatile("st.volatile.global.v4.f32 [%0], {%1,%2,%3,%4};"
                             :: "l"(dst), "f"(h_e), "f"(tagf), "f"(h_o), "f"(tagf)
                             : "memory");
            }
        }
    }
}

// ============== mma.sync split-bf16 GEMM machinery ==============
#define TILE_B  16384u
#define STAGE_B (4u * TILE_B)
#define SCORES_SMEM (2 * STAGE_B)
#define NCHUNK 24

__device__ __forceinline__ void load_stage(const __nv_bfloat16* Ah,
                                           const __nv_bfloat16* Al,
                                           const __nv_bfloat16* Bh,
                                           const __nv_bfloat16* Bl,
                                           int ld, int m0, int n0, int k0,
                                           uint32_t stage, int tid) {
#pragma unroll
    for (int i = 0; i < 16; i++) {
        int id = tid + (i << 8);
        int tile = id >> 10;
        int within = id & 1023;
        int row = within >> 3;
        int c = within & 7;
        const __nv_bfloat16* bp = (tile == 0) ? Ah : (tile == 1) ? Al
                                 : (tile == 2) ? Bh : Bl;
        int grow = ((tile < 2) ? m0 : n0) + row;
        const __nv_bfloat16* src = bp + (size_t)grow * ld + k0 + (c << 3);
        uint32_t dst = stage + ((uint32_t)tile << 14)
                     + sw128(((uint32_t)row << 7) + ((uint32_t)c << 4));
        cp16(dst, src);
    }
}

// one mainloop chunk (64-wide K): 3 product combos hi*hi + hi*lo + lo*hi
__device__ __forceinline__ void mma_chunk(uint32_t stg, int wm, int wn, int lane,
                                          float acc[2][8][4]) {
#pragma unroll
    for (int ks = 0; ks < 4; ks++) {
        uint32_t kbyte = ((uint32_t)ks << 5) + (((uint32_t)lane >> 4) << 4);
        uint32_t bh[4][4], bl[4][4];
#pragma unroll
        for (int q = 0; q < 4; q++) {
            uint32_t roff = ((uint32_t)(wn + q * 16 + (lane & 15))) << 7;
            LDSM4(bh[q], stg + (2u << 14) + sw128(roff + kbyte));
            LDSM4(bl[q], stg + (3u << 14) + sw128(roff + kbyte));
        }
#pragma unroll
        for (int mt = 0; mt < 2; mt++) {
            uint32_t roff = ((uint32_t)(wm + mt * 16 + (lane & 15))) << 7;
            uint32_t a_h[4], a_l[4];
            LDSM4(a_h, stg + sw128(roff + kbyte));
            LDSM4(a_l, stg + (1u << 14) + sw128(roff + kbyte));
#pragma unroll
            for (int q = 0; q < 4; q++) {
#pragma unroll
                for (int h = 0; h < 2; h++) {
                    int nt = q * 2 + h;
                    MMA16816(acc[mt][nt], a_h, bh[q][h], bh[q][h + 2]);
                    MMA16816(acc[mt][nt], a_h, bl[q][h], bl[q][h + 2]);
                    MMA16816(acc[mt][nt], a_l, bh[q][h], bh[q][h + 2]);
                }
            }
        }
    }
}

__device__ __forceinline__ void mma_epilogue(float acc[2][8][4], int wm, int wn,
                                             int lane, int m0, int n0,
                                             const float* bias, float* out, int ldc) {
#pragma unroll
    for (int mt = 0; mt < 2; mt++) {
        int mrow = m0 + wm + mt * 16 + (lane >> 2);
#pragma unroll
        for (int half = 0; half < 2; half++) {
            float* orow = out + (size_t)(mrow + half * 8) * ldc;
#pragma unroll
            for (int nt = 0; nt < 8; nt++) {
                int n = n0 + wn + nt * 8 + (lane & 3) * 2;
                float2 z = *(const float2*)&bias[n];
                float2 r;
                r.x = acc[mt][nt][half * 2 + 0] + z.x;
                r.y = acc[mt][nt][half * 2 + 1] + z.y;
                *(float2*)&orow[n] = r;
            }
        }
    }
}

// scores = hs@X^T (K=1024, 16 chunks) + embs@Y^T (K=512, 8 chunks) + zf
__global__ __launch_bounds__(256, 1)
void scores_mma_kernel(const __nv_bfloat16* __restrict__ Ah,
                       const __nv_bfloat16* __restrict__ Al,
                       const __nv_bfloat16* __restrict__ Xh,
                       const __nv_bfloat16* __restrict__ Xl,
                       const __nv_bfloat16* __restrict__ Eh,
                       const __nv_bfloat16* __restrict__ El,
                       const __nv_bfloat16* __restrict__ Yh,
                       const __nv_bfloat16* __restrict__ Yl,
                       const float* __restrict__ zf,
                       float* __restrict__ out) {
    extern __shared__ __align__(16) char dsm[];
    uint32_t base = smem_u32(dsm);
    const int tid = threadIdx.x, wid = tid >> 5, lane = tid & 31;
    const int m0 = blockIdx.x * 128, n0 = blockIdx.y * 128;
    const int wm = (wid & 3) * 32;
    const int wn = (wid >> 2) * 64;

    float acc[2][8][4];
#pragma unroll
    for (int a = 0; a < 2; a++)
#pragma unroll
        for (int b = 0; b < 8; b++)
#pragma unroll
            for (int c = 0; c < 4; c++) acc[a][b][c] = 0.f;

    load_stage(Ah, Al, Xh, Xl, STATE, m0, n0, 0, base, tid);
    CP_COMMIT();
    load_stage(Ah, Al, Xh, Xl, STATE, m0, n0, 64, base + STAGE_B, tid);
    CP_COMMIT();

#pragma unroll 1
    for (int s = 0; s < NCHUNK; s++) {
        uint32_t stg = base + (uint32_t)(s & 1) * STAGE_B;
        CP_WAIT1();
        __syncthreads();
        mma_chunk(stg, wm, wn, lane, acc);
        __syncthreads();
        if (s + 2 < NCHUNK) {
            int s2 = s + 2;
            if (s2 < 16)
                load_stage(Ah, Al, Xh, Xl, STATE, m0, n0, s2 * 64, stg, tid);
            else
                load_stage(Eh, El, Yh, Yl, EMBD, m0, n0, (s2 - 16) * 64, stg, tid);
            CP_COMMIT();
        }
    }
    mma_epilogue(acc, wm, wn, lane, m0, n0, zf, out, VOCAB);
}

// gates_x = embs @ W_ihE^T + gbias  (M=512, N=4096, K=512: 8 chunks)
__global__ __launch_bounds__(256, 1)
void gates_mma_kernel(const __nv_bfloat16* __restrict__ Ah,
                      const __nv_bfloat16* __restrict__ Al,
                      const __nv_bfloat16* __restrict__ Bh,
                      const __nv_bfloat16* __restrict__ Bl,
                      const float* __restrict__ bias,
                      float* __restrict__ out) {
    extern __shared__ __align__(16) char dsm[];
    uint32_t base = smem_u32(dsm);
    const int tid = threadIdx.x, wid = tid >> 5, lane = tid & 31;
    const int m0 = blockIdx.x * 128, n0 = blockIdx.y * 128;
    const int wm = (wid & 3) * 32;
    const int wn = (wid >> 2) * 64;

    float acc[2][8][4];
#pragma unroll
    for (int a = 0; a < 2; a++)
#pragma unroll
        for (int b = 0; b < 8; b++)
#pragma unroll
            for (int c = 0; c < 4; c++) acc[a][b][c] = 0.f;

    load_stage(Ah, Al, Bh, Bl, EMBD, m0, n0, 0, base, tid);
    CP_COMMIT();
    load_stage(Ah, Al, Bh, Bl, EMBD, m0, n0, 64, base + STAGE_B, tid);
    CP_COMMIT();

#pragma unroll 1
    for (int s = 0; s < 8; s++) {
        uint32_t stg = base + (uint32_t)(s & 1) * STAGE_B;
        CP_WAIT1();
        __syncthreads();
        mma_chunk(stg, wm, wn, lane, acc);
        __syncthreads();
        if (s + 2 < 8) {
            load_stage(Ah, Al, Bh, Bl, EMBD, m0, n0, (s + 2) * 64, stg, tid);
            CP_COMMIT();
        }
    }
    mma_epilogue(acc, wm, wn, lane, m0, n0, bias, out, G4);
}

// ---------------- launch ----------------
extern "C" void kernel_launch(void* const* d_in, const int* in_sizes, int n_in,
                              void* d_out, int out_size) {
    (void)in_sizes; (void)n_in; (void)out_size;
    const float* h0   = (const float*)d_in[0];
    const float* c0   = (const float*)d_in[1];
    const int*   ids  = (const int*)d_in[2];
    const float* embT = (const float*)d_in[3];
    const float* W_ih = (const float*)d_in[4];
    const float* W_hh = (const float*)d_in[5];
    const float* b_ih = (const float*)d_in[6];
    const float* b_hh = (const float*)d_in[7];
    const float* X    = (const float*)d_in[8];
    const float* Y    = (const float*)d_in[9];
    const float* Z    = (const float*)d_in[10];
    float* out = (float*)d_out;

    float *p_embs, *p_gbias, *p_zf, *p_gatesx, *p_hs;
    cudaGetSymbolAddress((void**)&p_embs, g_embs);
    cudaGetSymbolAddress((void**)&p_gbias, g_gbias);
    cudaGetSymbolAddress((void**)&p_zf, g_zf);
    cudaGetSymbolAddress((void**)&p_gatesx, g_gatesx);
    cudaGetSymbolAddress((void**)&p_hs, g_hs);
    __nv_bfloat16 *pXh, *pXl, *pYh, *pYl, *pHh, *pHl, *pEh, *pEl, *pWh, *pWl;
    cudaGetSymbolAddress((void**)&pXh, g_X_hi);
    cudaGetSymbolAddress((void**)&pXl, g_X_lo);
    cudaGetSymbolAddress((void**)&pYh, g_Y_hi);
    cudaGetSymbolAddress((void**)&pYl, g_Y_lo);
    cudaGetSymbolAddress((void**)&pHh, g_hs_hi);
    cudaGetSymbolAddress((void**)&pHl, g_hs_lo);
    cudaGetSymbolAddress((void**)&pEh, g_e_hi);
    cudaGetSymbolAddress((void**)&pEl, g_e_lo);
    cudaGetSymbolAddress((void**)&pWh, g_Wx_hi);
    cudaGetSymbolAddress((void**)&pWl, g_Wx_lo);

    // 1) gather embeddings, reset tagged slots
    prep_kernel<<<T_STEPS, 128>>>(ids, embT);

    // 2) gbias = b_ih + b_hh + W_ih[:,E:] @ fixed
    rowdot_kernel<<<G4 / 8, 256>>>(W_ih + EMBD, (EMBD + 2 * STATE) / 4,
                                   h0, c0, b_ih, b_hh, p_gbias);

    // 3) zf = Z @ fixed
    rowdot_kernel<<<VOCAB / 8, 256>>>(Z, (2 * STATE) / 4,
                                      h0, c0, nullptr, nullptr, p_zf);

    // 4) split conversions: X, Y, embs, W_ihE (strided)
    conv_split_kernel<<<(VOCAB * STATE / 4 + 255) / 256, 256>>>(X, pXh, pXl,
                                                                VOCAB * STATE / 4);
    conv_split_kernel<<<(VOCAB * EMBD / 4 + 255) / 256, 256>>>(Y, pYh, pYl,
                                                               VOCAB * EMBD / 4);
    conv_split_kernel<<<(T_STEPS * EMBD / 4 + 255) / 256, 256>>>(p_embs, pEh, pEl,
                                                                 T_STEPS * EMBD / 4);
    conv_split_strided_kernel<<<(G4 * EMBD / 4 + 255) / 256, 256>>>(
        W_ih, (EMBD + 2 * STATE) / 4, EMBD / 4, pWh, pWl, G4 * EMBD / 4);

    // 5) gates_x = embs @ W_ihE^T + gbias via split-bf16 mma
    {
        cudaFuncSetAttribute(gates_mma_kernel,
                             cudaFuncAttributeMaxDynamicSharedMemorySize, SCORES_SMEM);
        dim3 grid(T_STEPS / 128, G4 / 128);
        gates_mma_kernel<<<grid, 256, SCORES_SMEM>>>(pEh, pEl, pWh, pWl,
                                                     p_gbias, p_gatesx);
    }

    // 6) sequential LSTM scan (v8: warp-local consumption)
    scan_kernel<<<128, 512>>>(W_hh, h0, c0);

    // 7) hs -> hi/lo bf16
    conv_split_kernel<<<(T_STEPS * STATE / 4 + 255) / 256, 256>>>(p_hs, pHh, pHl,
                                                                  T_STEPS * STATE / 4);

    // 8) scores = hs@X^T + embs@Y^T + zf via split-bf16 mma
    {
        cudaFuncSetAttribute(scores_mma_kernel,
                             cudaFuncAttributeMaxDynamicSharedMemorySize, SCORES_SMEM);
        dim3 grid(T_STEPS / 128, VOCAB / 128);
        scores_mma_kernel<<<grid, 256, SCORES_SMEM>>>(pHh, pHl, pXh, pXl,
                                                      pEh, pEl, pYh, pYl,
                                                      p_zf, out);
    }
}